// round 1
// baseline (speedup 1.0000x reference)
#include <cuda_runtime.h>
#include <math_constants.h>

#define Bn 64
#define Ln 4096
#define Nn 128
#define Fn 2049
#define N2h 2048
#define En 8
#define NSER (Bn * Nn)  // 8192

// ---------------- scratch (static device globals; no allocation) ----------------
__device__ float  g_xt[(size_t)NSER * Ln];    // [B*N, L] time series; reused for reconstruction
__device__ float2 g_freq[(size_t)NSER * Fn];  // [B*N, F] rfft output
__device__ float  g_mean[NSER];
__device__ float  g_std[NSER];
__device__ float  g_mag[Bn * Fn];
__device__ float  g_h[Bn * Fn];
__device__ float  g_wmask[Bn * Fn];
__device__ int    g_bandOf[Fn];

__device__ __forceinline__ float2 cmulf(float2 a, float2 b) {
    return make_float2(a.x * b.x - a.y * b.y, a.x * b.y + a.y * b.x);
}

// ---------------- K0: band boundaries -> per-bin expert index ----------------
__global__ void k_band(const float* __restrict__ bb) {
    __shared__ int idx[9];
    if (threadIdx.x == 0) {
        float v[7];
        #pragma unroll
        for (int i = 0; i < 7; i++) v[i] = 1.f / (1.f + expf(-bb[i]));
        // insertion sort (7 elems)
        for (int i = 1; i < 7; i++) {
            float key = v[i]; int j = i - 1;
            while (j >= 0 && v[j] > key) { v[j + 1] = v[j]; j--; }
            v[j + 1] = key;
        }
        idx[0] = 0;
        for (int e = 1; e < 8; e++) {
            int t = (int)(v[e - 1] * 2049.0f);  // trunc toward zero, matches .astype(int32)
            idx[e] = min(max(t, 0), 2049);
        }
        idx[8] = 2049;
    }
    __syncthreads();
    for (int f = threadIdx.x; f < Fn; f += blockDim.x) {
        int e = 0;
        #pragma unroll
        for (int t = 0; t < 8; t++)
            if (f >= idx[t] && f < idx[t + 1]) { e = t; break; }
        g_bandOf[f] = e;
    }
}

// ---------------- K1: transpose x [B,L,N] -> g_xt [B,N,L] ----------------
__global__ void k_transpose_in(const float* __restrict__ x) {
    __shared__ float tile[32][33];
    int b = blockIdx.z;
    int l0 = blockIdx.x * 32, n0 = blockIdx.y * 32;
    int tx = threadIdx.x, ty = threadIdx.y;  // 32 x 8
    #pragma unroll
    for (int j = 0; j < 32; j += 8)
        tile[ty + j][tx] = x[((size_t)(b * Ln + l0 + ty + j)) * Nn + n0 + tx];
    __syncthreads();
    #pragma unroll
    for (int j = 0; j < 32; j += 8)
        g_xt[((size_t)(b * Nn + n0 + ty + j)) * Ln + l0 + tx] = tile[tx][ty + j];
}

// ---------------- shared 2048-pt Stockham FFT (256 threads) ----------------
// Returns pointer to the buffer holding the result (natural order).
__device__ float2* fft2048(float2* bufA, float2* bufB, float sign, int tid) {
    float2* src = bufA;
    float2* dst = bufB;
    int m = 1024, ls = 0;
    for (int stage = 0; stage < 11; stage++) {
        int s = 1 << ls;
        float ascale = sign * CUDART_PI_F / (float)m;
        #pragma unroll
        for (int i = 0; i < 4; i++) {
            int u = tid + (i << 8);     // 0..1023
            int q = u & (s - 1);
            int p = u >> ls;
            float2 a = src[q + (p << ls)];
            float2 b = src[q + ((p + m) << ls)];
            float2 sum = make_float2(a.x + b.x, a.y + b.y);
            float2 dif = make_float2(a.x - b.x, a.y - b.y);
            float c, sn;
            __sincosf(ascale * (float)p, &sn, &c);
            dst[q + ((2 * p) << ls)]     = sum;
            dst[q + ((2 * p + 1) << ls)] = cmulf(dif, make_float2(c, sn));
        }
        __syncthreads();
        float2* t = src; src = dst; dst = t;
        m >>= 1; ls++;
    }
    return src;
}

// ---------------- K2: per-series mean/var + rfft ----------------
__global__ __launch_bounds__(256) void k_fwd() {
    __shared__ float2 sA[2048];
    __shared__ float2 sB[2048];
    __shared__ float  sred[16];
    int series = blockIdx.x;
    int tid = threadIdx.x;
    const float2* row = (const float2*)(g_xt + (size_t)series * Ln);
    float s1 = 0.f, s2 = 0.f;
    for (int m = tid; m < 2048; m += 256) {
        float2 v = row[m];
        sA[m] = v;
        s1 += v.x + v.y;
        s2 += v.x * v.x + v.y * v.y;
    }
    #pragma unroll
    for (int off = 16; off; off >>= 1) {
        s1 += __shfl_down_sync(~0u, s1, off);
        s2 += __shfl_down_sync(~0u, s2, off);
    }
    if ((tid & 31) == 0) { sred[tid >> 5] = s1; sred[8 + (tid >> 5)] = s2; }
    __syncthreads();
    if (tid == 0) {
        float a = 0.f, bsum = 0.f;
        #pragma unroll
        for (int w = 0; w < 8; w++) { a += sred[w]; bsum += sred[8 + w]; }
        float mean = a * (1.f / 4096.f);
        float var = bsum * (1.f / 4096.f) - mean * mean + 1e-6f;
        g_mean[series] = mean;
        g_std[series]  = sqrtf(fmaxf(var, 0.f));
    }
    __syncthreads();

    float2* Z = fft2048(sA, sB, -1.f, tid);

    // untangle packed FFT -> rfft bins X[0..2048]
    float2* out = g_freq + (size_t)series * Fn;
    for (int k = tid; k < Fn; k += 256) {
        float2 zk  = Z[k & (N2h - 1)];
        float2 zmk = Z[(N2h - k) & (N2h - 1)];
        float2 A  = make_float2(0.5f * (zk.x + zmk.x), 0.5f * (zk.y - zmk.y));
        float dx = zk.x - zmk.x, dy = zk.y + zmk.y;
        float2 Bv = make_float2(0.5f * dy, -0.5f * dx);   // -0.5i * d
        float c, sn;
        __sincosf(-(CUDART_PI_F / 2048.f) * (float)k, &sn, &c);
        out[k] = make_float2(A.x + c * Bv.x - sn * Bv.y,
                             A.y + c * Bv.y + sn * Bv.x);
    }
}

// ---------------- K3: mag[b,f] = mean_n |freq[b,n,f]| ----------------
__global__ __launch_bounds__(256) void k_mag() {
    int f = blockIdx.x * 256 + threadIdx.x;
    int b = blockIdx.y;
    if (f >= Fn) return;
    const float2* base = g_freq + (size_t)b * Nn * Fn + f;
    float s = 0.f;
    #pragma unroll 4
    for (int n = 0; n < Nn; n++) {
        float2 v = base[(size_t)n * Fn];
        s += sqrtf(v.x * v.x + v.y * v.y);
    }
    g_mag[b * Fn + f] = s * (1.f / 128.f);
}

// ---------------- K4: h = relu(mag @ W1 + b1), [64,2049]x[2049,2049] ----------------
__global__ __launch_bounds__(256) void k_gemm1(const float* __restrict__ w1,
                                               const float* __restrict__ b1) {
    __shared__ float sMag[64 * 32];   // [row b][kk]
    __shared__ float sW[32 * 33];     // [kk][j], padded
    int j0 = blockIdx.x * 32;
    int tid = threadIdx.x;
    int tj = tid & 31, tr = tid >> 5;  // tr 0..7
    float acc[8];
    #pragma unroll
    for (int r = 0; r < 8; r++) acc[r] = 0.f;

    for (int k0 = 0; k0 < Fn; k0 += 32) {
        for (int t = tid; t < 2048; t += 256) {
            int bb = t >> 5, kk = t & 31;
            int k = k0 + kk;
            sMag[t] = (k < Fn) ? g_mag[bb * Fn + k] : 0.f;
        }
        for (int t = tid; t < 1024; t += 256) {
            int kk = t >> 5, j = t & 31;
            int k = k0 + kk, jj = j0 + j;
            sW[kk * 33 + j] = (k < Fn && jj < Fn) ? w1[(size_t)k * Fn + jj] : 0.f;
        }
        __syncthreads();
        #pragma unroll
        for (int kk = 0; kk < 32; kk++) {
            float wv = sW[kk * 33 + tj];
            #pragma unroll
            for (int r = 0; r < 8; r++)
                acc[r] = fmaf(sMag[(tr + 8 * r) * 32 + kk], wv, acc[r]);
        }
        __syncthreads();
    }
    int j = j0 + tj;
    if (j < Fn) {
        float bias = b1[j];
        #pragma unroll
        for (int r = 0; r < 8; r++) {
            int bb = tr + 8 * r;
            g_h[bb * Fn + j] = fmaxf(acc[r] + bias, 0.f);
        }
    }
}

// ---------------- K5: logits -> softmax -> wmask[b,f] ----------------
__global__ __launch_bounds__(256) void k_gate2(const float* __restrict__ w2,
                                               const float* __restrict__ b2) {
    __shared__ float slog[8];
    __shared__ float sw[8];
    int b = blockIdx.x;
    int tid = threadIdx.x, warp = tid >> 5, lane = tid & 31;
    float part = 0.f;
    for (int k = lane; k < Fn; k += 32)
        part += g_h[b * Fn + k] * w2[k * En + warp];
    #pragma unroll
    for (int off = 16; off; off >>= 1) part += __shfl_down_sync(~0u, part, off);
    if (lane == 0) slog[warp] = part + b2[warp];
    __syncthreads();
    if (tid == 0) {
        float mx = -1e30f;
        for (int e = 0; e < 8; e++) mx = fmaxf(mx, slog[e]);
        float s = 0.f, ex[8];
        for (int e = 0; e < 8; e++) { ex[e] = expf(slog[e] - mx); s += ex[e]; }
        float inv = 1.f / s;
        for (int e = 0; e < 8; e++) sw[e] = ex[e] * inv;
    }
    __syncthreads();
    for (int f = tid; f < Fn; f += 256)
        g_wmask[b * Fn + f] = sw[g_bandOf[f]];
}

// ---------------- K6: filter + irfft, write rec*std+mean into g_xt ----------------
__global__ __launch_bounds__(256) void k_inv() {
    __shared__ float2 sA[2048];
    __shared__ float2 sB[2048];
    __shared__ float2 sX2048;
    int series = blockIdx.x;
    int b = series >> 7;  // /128
    int tid = threadIdx.x;
    const float2* Xg = g_freq + (size_t)series * Fn;
    const float*  wm = g_wmask + b * Fn;

    for (int k = tid; k < 2048; k += 256) {
        float2 v = Xg[k];
        float w = wm[k];
        sA[k] = make_float2(v.x * w, v.y * w);
    }
    if (tid == 0) {
        float2 v = Xg[2048];
        float w = wm[2048];
        sX2048 = make_float2(v.x * w, v.y * w);
    }
    __syncthreads();

    // repack rfft bins -> Z[0..2047] in place (paired k, 2048-k per thread)
    for (int k = tid; k <= 1024; k += 256) {
        float2 Xk  = sA[k];
        float2 Xmk = (k == 0) ? sX2048 : sA[2048 - k];
        float2 A = make_float2(0.5f * (Xk.x + Xmk.x), 0.5f * (Xk.y - Xmk.y));
        float dx = Xk.x - Xmk.x, dy = Xk.y + Xmk.y;
        float c, sn;
        __sincosf((CUDART_PI_F / 2048.f) * (float)k, &sn, &c);
        float2 Bc = make_float2(0.5f * (c * dx - sn * dy), 0.5f * (c * dy + sn * dx));
        sA[k] = make_float2(A.x - Bc.y, A.y + Bc.x);          // Z[k] = A + iB
        if (k >= 1 && k < 1024)
            sA[2048 - k] = make_float2(A.x + Bc.y, Bc.x - A.y);  // conj(A - iB)
    }
    __syncthreads();

    float2* Zt = fft2048(sA, sB, +1.f, tid);  // unnormalized inverse

    float2* outrow = (float2*)(g_xt + (size_t)series * Ln);
    float mean = g_mean[series];
    float stdv = g_std[series];
    const float inv = 1.f / 2048.f;
    for (int m = tid; m < 2048; m += 256) {
        float2 z = Zt[m];
        outrow[m] = make_float2(fmaf(z.x * inv, stdv, mean),
                                fmaf(z.y * inv, stdv, mean));
    }
}

// ---------------- K7: out[b,l,n] = x[b,l,n] + rec[b,n,l] ----------------
__global__ void k_transpose_out(const float* __restrict__ x, float* __restrict__ out) {
    __shared__ float tile[32][33];
    int b = blockIdx.z;
    int l0 = blockIdx.x * 32, n0 = blockIdx.y * 32;
    int tx = threadIdx.x, ty = threadIdx.y;
    #pragma unroll
    for (int j = 0; j < 32; j += 8)
        tile[ty + j][tx] = g_xt[((size_t)(b * Nn + n0 + ty + j)) * Ln + l0 + tx];
    __syncthreads();
    #pragma unroll
    for (int j = 0; j < 32; j += 8) {
        size_t o = ((size_t)(b * Ln + l0 + ty + j)) * Nn + n0 + tx;
        out[o] = x[o] + tile[tx][ty + j];
    }
}

extern "C" void kernel_launch(void* const* d_in, const int* in_sizes, int n_in,
                              void* d_out, int out_size) {
    const float* x  = (const float*)d_in[0];
    const float* bb = (const float*)d_in[1];
    const float* w1 = (const float*)d_in[2];
    const float* b1 = (const float*)d_in[3];
    const float* w2 = (const float*)d_in[4];
    const float* b2 = (const float*)d_in[5];
    float* out = (float*)d_out;

    dim3 tb(32, 8);
    k_band<<<1, 256>>>(bb);
    k_transpose_in<<<dim3(128, 4, 64), tb>>>(x);
    k_fwd<<<NSER, 256>>>();
    k_mag<<<dim3(9, 64), 256>>>();
    k_gemm1<<<65, 256>>>(w1, b1);
    k_gate2<<<64, 256>>>(w2, b2);
    k_inv<<<NSER, 256>>>();
    k_transpose_out<<<dim3(128, 4, 64), tb>>>(x, out);
}

// round 2
// speedup vs baseline: 1.2805x; 1.2805x over previous
#include <cuda_runtime.h>
#include <math_constants.h>

#define Bn 64
#define Ln 4096
#define Nn 128
#define Fn 2049
#define N2h 2048
#define En 8
#define NSER (Bn * Nn)  // 8192

// ---------------- scratch (static device globals; no allocation) ----------------
__device__ float  g_xt[(size_t)NSER * Ln];    // [B*N, L] time series; reused for reconstruction
__device__ float2 g_freq[(size_t)NSER * Fn];  // [B*N, F] rfft output
__device__ float  g_mean[NSER];
__device__ float  g_std[NSER];
__device__ float  g_mag[Bn * Fn];
__device__ float  g_h[Bn * Fn];
__device__ float  g_wmask[Bn * Fn];
__device__ int    g_bandOf[Fn];
__device__ float2 g_T[1025];                  // T[i] = exp(-i*pi*i/2048), i=0..1024

__device__ __forceinline__ float2 cmulf(float2 a, float2 b) {
    return make_float2(a.x * b.x - a.y * b.y, a.x * b.y + a.y * b.x);
}

// lookup exp(-i*pi*idx/2048) for idx in [0, 2048] from half-table
__device__ __forceinline__ float2 tw_lookup(const float2* __restrict__ T, int idx) {
    if (idx <= 1024) return T[idx];
    float2 u = T[2048 - idx];
    return make_float2(-u.x, u.y);  // -conj(T[j]) where T[j]=(c,-s)
}

// ---------------- K-1: init twiddle table ----------------
__global__ void k_init_tw() {
    int k = blockIdx.x * 256 + threadIdx.x;
    if (k <= 1024) {
        float s, c;
        sincosf(CUDART_PI_F * (float)k / 2048.f, &s, &c);
        g_T[k] = make_float2(c, -s);
    }
}

// ---------------- K0: band boundaries -> per-bin expert index ----------------
__global__ void k_band(const float* __restrict__ bb) {
    __shared__ int idx[9];
    if (threadIdx.x == 0) {
        float v[7];
        #pragma unroll
        for (int i = 0; i < 7; i++) v[i] = 1.f / (1.f + expf(-bb[i]));
        for (int i = 1; i < 7; i++) {
            float key = v[i]; int j = i - 1;
            while (j >= 0 && v[j] > key) { v[j + 1] = v[j]; j--; }
            v[j + 1] = key;
        }
        idx[0] = 0;
        for (int e = 1; e < 8; e++) {
            int t = (int)(v[e - 1] * 2049.0f);  // trunc toward zero, matches .astype(int32)
            idx[e] = min(max(t, 0), 2049);
        }
        idx[8] = 2049;
    }
    __syncthreads();
    for (int f = threadIdx.x; f < Fn; f += blockDim.x) {
        int e = 0;
        #pragma unroll
        for (int t = 0; t < 8; t++)
            if (f >= idx[t] && f < idx[t + 1]) { e = t; break; }
        g_bandOf[f] = e;
    }
}

// ---------------- K1: transpose x [B,L,N] -> g_xt [B,N,L] ----------------
__global__ void k_transpose_in(const float* __restrict__ x) {
    __shared__ float tile[32][33];
    int b = blockIdx.z;
    int l0 = blockIdx.x * 32, n0 = blockIdx.y * 32;
    int tx = threadIdx.x, ty = threadIdx.y;  // 32 x 8
    #pragma unroll
    for (int j = 0; j < 32; j += 8)
        tile[ty + j][tx] = x[((size_t)(b * Ln + l0 + ty + j)) * Nn + n0 + tx];
    __syncthreads();
    #pragma unroll
    for (int j = 0; j < 32; j += 8)
        g_xt[((size_t)(b * Nn + n0 + ty + j)) * Ln + l0 + tx] = tile[tx][ty + j];
}

// ---------------- shared 2048-pt Stockham FFT (256 threads, table twiddles) ----------------
// CONJ=0: forward (exp(-i...)); CONJ=1: inverse (exp(+i...), unnormalized)
template <int CONJ>
__device__ float2* fft2048_t(float2* src, float2* dst, const float2* __restrict__ T, int tid) {
    int m = 1024;
    for (int stage = 0; stage < 11; stage++) {
        int s = 1 << stage;
        #pragma unroll
        for (int i = 0; i < 4; i++) {
            int u = tid + (i << 8);     // 0..1023
            int q = u & (s - 1);
            int p = u >> stage;
            float2 a = src[q + (p << stage)];
            float2 b = src[q + ((p + m) << stage)];
            float2 sum = make_float2(a.x + b.x, a.y + b.y);
            float2 dif = make_float2(a.x - b.x, a.y - b.y);
            float2 w = tw_lookup(T, p << (stage + 1));
            if (CONJ) w.y = -w.y;
            dst[q + ((2 * p) << stage)]     = sum;
            dst[q + ((2 * p + 1) << stage)] = cmulf(dif, w);
        }
        __syncthreads();
        float2* t = src; src = dst; dst = t;
        m >>= 1;
    }
    return src;
}

// ---------------- K2: per-series mean/var + rfft ----------------
__global__ __launch_bounds__(256) void k_fwd() {
    __shared__ float2 sA[2048];
    __shared__ float2 sB[2048];
    __shared__ float2 sT[1025];
    __shared__ float  sred[16];
    int series = blockIdx.x;
    int tid = threadIdx.x;

    for (int i = tid; i < 1025; i += 256) sT[i] = g_T[i];

    const float2* row = (const float2*)(g_xt + (size_t)series * Ln);
    float s1 = 0.f, s2 = 0.f;
    for (int m = tid; m < 2048; m += 256) {
        float2 v = row[m];
        sA[m] = v;
        s1 += v.x + v.y;
        s2 += v.x * v.x + v.y * v.y;
    }
    #pragma unroll
    for (int off = 16; off; off >>= 1) {
        s1 += __shfl_down_sync(~0u, s1, off);
        s2 += __shfl_down_sync(~0u, s2, off);
    }
    if ((tid & 31) == 0) { sred[tid >> 5] = s1; sred[8 + (tid >> 5)] = s2; }
    __syncthreads();
    if (tid == 0) {
        float a = 0.f, bsum = 0.f;
        #pragma unroll
        for (int w = 0; w < 8; w++) { a += sred[w]; bsum += sred[8 + w]; }
        float mean = a * (1.f / 4096.f);
        float var = bsum * (1.f / 4096.f) - mean * mean + 1e-6f;
        g_mean[series] = mean;
        g_std[series]  = sqrtf(fmaxf(var, 0.f));
    }
    __syncthreads();

    float2* Z = fft2048_t<0>(sA, sB, sT, tid);

    // untangle packed FFT -> rfft bins X[0..2048]
    float2* out = g_freq + (size_t)series * Fn;
    for (int k = tid; k < Fn; k += 256) {
        float2 zk  = Z[k & (N2h - 1)];
        float2 zmk = Z[(N2h - k) & (N2h - 1)];
        float2 A  = make_float2(0.5f * (zk.x + zmk.x), 0.5f * (zk.y - zmk.y));
        float dx = zk.x - zmk.x, dy = zk.y + zmk.y;
        float2 Bv = make_float2(0.5f * dy, -0.5f * dx);   // -0.5i * d
        float2 t = tw_lookup(sT, k);                      // (cos, -sin)
        out[k] = make_float2(A.x + t.x * Bv.x - t.y * Bv.y,
                             A.y + t.x * Bv.y + t.y * Bv.x);
    }
}

// ---------------- K3: mag[b,f] = mean_n |freq[b,n,f]| ----------------
__global__ __launch_bounds__(256) void k_mag() {
    int f = blockIdx.x * 256 + threadIdx.x;
    int b = blockIdx.y;
    if (f >= Fn) return;
    const float2* base = g_freq + (size_t)b * Nn * Fn + f;
    float acc[8];
    #pragma unroll
    for (int j = 0; j < 8; j++) acc[j] = 0.f;
    #pragma unroll 2
    for (int n0 = 0; n0 < Nn; n0 += 8) {
        #pragma unroll
        for (int j = 0; j < 8; j++) {
            float2 v = base[(size_t)(n0 + j) * Fn];
            acc[j] += sqrtf(v.x * v.x + v.y * v.y);
        }
    }
    float s = ((acc[0] + acc[1]) + (acc[2] + acc[3])) +
              ((acc[4] + acc[5]) + (acc[6] + acc[7]));
    g_mag[b * Fn + f] = s * (1.f / 128.f);
}

// ---------------- K4: h = relu(mag @ W1 + b1), [64,2049]x[2049,2049] ----------------
__global__ __launch_bounds__(256) void k_gemm1(const float* __restrict__ w1,
                                               const float* __restrict__ b1) {
    __shared__ float sMag[64 * 32];   // [row b][kk]
    __shared__ float sW[32 * 33];     // [kk][j], padded
    int j0 = blockIdx.x * 32;
    int tid = threadIdx.x;
    int tj = tid & 31, tr = tid >> 5;  // tr 0..7
    float acc[8];
    #pragma unroll
    for (int r = 0; r < 8; r++) acc[r] = 0.f;

    for (int k0 = 0; k0 < Fn; k0 += 32) {
        for (int t = tid; t < 2048; t += 256) {
            int bb = t >> 5, kk = t & 31;
            int k = k0 + kk;
            sMag[t] = (k < Fn) ? g_mag[bb * Fn + k] : 0.f;
        }
        for (int t = tid; t < 1024; t += 256) {
            int kk = t >> 5, j = t & 31;
            int k = k0 + kk, jj = j0 + j;
            sW[kk * 33 + j] = (k < Fn && jj < Fn) ? w1[(size_t)k * Fn + jj] : 0.f;
        }
        __syncthreads();
        #pragma unroll
        for (int kk = 0; kk < 32; kk++) {
            float wv = sW[kk * 33 + tj];
            #pragma unroll
            for (int r = 0; r < 8; r++)
                acc[r] = fmaf(sMag[(tr + 8 * r) * 32 + kk], wv, acc[r]);
        }
        __syncthreads();
    }
    int j = j0 + tj;
    if (j < Fn) {
        float bias = b1[j];
        #pragma unroll
        for (int r = 0; r < 8; r++) {
            int bb = tr + 8 * r;
            g_h[bb * Fn + j] = fmaxf(acc[r] + bias, 0.f);
        }
    }
}

// ---------------- K5: logits -> softmax -> wmask[b,f] ----------------
__global__ __launch_bounds__(256) void k_gate2(const float* __restrict__ w2,
                                               const float* __restrict__ b2) {
    __shared__ float slog[8];
    __shared__ float sw[8];
    int b = blockIdx.x;
    int tid = threadIdx.x, warp = tid >> 5, lane = tid & 31;
    float part = 0.f;
    for (int k = lane; k < Fn; k += 32)
        part += g_h[b * Fn + k] * w2[k * En + warp];
    #pragma unroll
    for (int off = 16; off; off >>= 1) part += __shfl_down_sync(~0u, part, off);
    if (lane == 0) slog[warp] = part + b2[warp];
    __syncthreads();
    if (tid == 0) {
        float mx = -1e30f;
        for (int e = 0; e < 8; e++) mx = fmaxf(mx, slog[e]);
        float s = 0.f, ex[8];
        for (int e = 0; e < 8; e++) { ex[e] = expf(slog[e] - mx); s += ex[e]; }
        float inv = 1.f / s;
        for (int e = 0; e < 8; e++) sw[e] = ex[e] * inv;
    }
    __syncthreads();
    for (int f = tid; f < Fn; f += 256)
        g_wmask[b * Fn + f] = sw[g_bandOf[f]];
}

// ---------------- K6: filter + irfft, write rec*std+mean into g_xt ----------------
__global__ __launch_bounds__(256) void k_inv() {
    __shared__ float2 sA[2048];
    __shared__ float2 sB[2048];
    __shared__ float2 sT[1025];
    __shared__ float2 sX2048;
    int series = blockIdx.x;
    int b = series >> 7;  // /128
    int tid = threadIdx.x;
    const float2* Xg = g_freq + (size_t)series * Fn;
    const float*  wm = g_wmask + b * Fn;

    for (int i = tid; i < 1025; i += 256) sT[i] = g_T[i];

    for (int k = tid; k < 2048; k += 256) {
        float2 v = Xg[k];
        float w = wm[k];
        sA[k] = make_float2(v.x * w, v.y * w);
    }
    if (tid == 0) {
        float2 v = Xg[2048];
        float w = wm[2048];
        sX2048 = make_float2(v.x * w, v.y * w);
    }
    __syncthreads();

    // repack rfft bins -> Z[0..2047] in place (paired k, 2048-k per thread)
    for (int k = tid; k <= 1024; k += 256) {
        float2 Xk  = sA[k];
        float2 Xmk = (k == 0) ? sX2048 : sA[2048 - k];
        float2 A = make_float2(0.5f * (Xk.x + Xmk.x), 0.5f * (Xk.y - Xmk.y));
        float dx = Xk.x - Xmk.x, dy = Xk.y + Xmk.y;
        float2 t = sT[k];            // (cos, -sin)
        float c = t.x, sn = -t.y;    // need exp(+i...) components
        float2 Bc = make_float2(0.5f * (c * dx - sn * dy), 0.5f * (c * dy + sn * dx));
        sA[k] = make_float2(A.x - Bc.y, A.y + Bc.x);          // Z[k] = A + iB
        if (k >= 1 && k < 1024)
            sA[2048 - k] = make_float2(A.x + Bc.y, Bc.x - A.y);  // conj(A - iB)
    }
    __syncthreads();

    float2* Zt = fft2048_t<1>(sA, sB, sT, tid);  // unnormalized inverse

    float2* outrow = (float2*)(g_xt + (size_t)series * Ln);
    float mean = g_mean[series];
    float stdv = g_std[series];
    const float inv = 1.f / 2048.f;
    for (int m = tid; m < 2048; m += 256) {
        float2 z = Zt[m];
        outrow[m] = make_float2(fmaf(z.x * inv, stdv, mean),
                                fmaf(z.y * inv, stdv, mean));
    }
}

// ---------------- K7: out[b,l,n] = x[b,l,n] + rec[b,n,l] ----------------
__global__ void k_transpose_out(const float* __restrict__ x, float* __restrict__ out) {
    __shared__ float tile[32][33];
    int b = blockIdx.z;
    int l0 = blockIdx.x * 32, n0 = blockIdx.y * 32;
    int tx = threadIdx.x, ty = threadIdx.y;
    #pragma unroll
    for (int j = 0; j < 32; j += 8)
        tile[ty + j][tx] = g_xt[((size_t)(b * Nn + n0 + ty + j)) * Ln + l0 + tx];
    __syncthreads();
    #pragma unroll
    for (int j = 0; j < 32; j += 8) {
        size_t o = ((size_t)(b * Ln + l0 + ty + j)) * Nn + n0 + tx;
        out[o] = x[o] + tile[tx][ty + j];
    }
}

extern "C" void kernel_launch(void* const* d_in, const int* in_sizes, int n_in,
                              void* d_out, int out_size) {
    const float* x  = (const float*)d_in[0];
    const float* bb = (const float*)d_in[1];
    const float* w1 = (const float*)d_in[2];
    const float* b1 = (const float*)d_in[3];
    const float* w2 = (const float*)d_in[4];
    const float* b2 = (const float*)d_in[5];
    float* out = (float*)d_out;

    dim3 tb(32, 8);
    k_init_tw<<<5, 256>>>();
    k_band<<<1, 256>>>(bb);
    k_transpose_in<<<dim3(128, 4, 64), tb>>>(x);
    k_fwd<<<NSER, 256>>>();
    k_mag<<<dim3(9, 64), 256>>>();
    k_gemm1<<<65, 256>>>(w1, b1);
    k_gate2<<<64, 256>>>(w2, b2);
    k_inv<<<NSER, 256>>>();
    k_transpose_out<<<dim3(128, 4, 64), tb>>>(x, out);
}

// round 3
// speedup vs baseline: 1.5377x; 1.2009x over previous
#include <cuda_runtime.h>
#include <math_constants.h>

#define Bn 64
#define Ln 4096
#define Nn 128
#define Fn 2049
#define N2h 2048
#define En 8
#define NSER (Bn * Nn)  // 8192

#define C_SQ 0.70710678118654752f
#define PADi(i) ((i) + ((i) >> 3))

// ---------------- scratch ----------------
__device__ float  g_xt[(size_t)NSER * Ln];
__device__ float2 g_freq[(size_t)NSER * Fn];
__device__ float  g_mean[NSER];
__device__ float  g_std[NSER];
__device__ float  g_mag[Bn * Fn];
__device__ float  g_h[Bn * Fn];
__device__ float  g_wmask[Bn * Fn];
__device__ int    g_bandOf[Fn];
__device__ float2 g_T[1025];   // T[i] = exp(-i*pi*i/2048) = W_4096^i, i=0..1024

struct cpx { float x, y; };
__device__ __forceinline__ cpx cmul(cpx a, cpx b) {
    return cpx{a.x * b.x - a.y * b.y, a.x * b.y + a.y * b.x};
}
__device__ __forceinline__ void fft2p(cpx& a, cpx& b) {
    cpx t{a.x - b.x, a.y - b.y};
    a = cpx{a.x + b.x, a.y + b.y};
    b = t;
}
// multiply by -i (fwd) / +i (inv)
template <int CONJ> __device__ __forceinline__ cpx mul_mi(cpx a) {
    return CONJ ? cpx{-a.y, a.x} : cpx{a.y, -a.x};
}
// W8^1 = (1-i)/sqrt2 fwd; conj for inv
template <int CONJ> __device__ __forceinline__ cpx mul_w81(cpx a) {
    return CONJ ? cpx{C_SQ * (a.x - a.y), C_SQ * (a.y + a.x)}
                : cpx{C_SQ * (a.x + a.y), C_SQ * (a.y - a.x)};
}
// W8^3 = (-1-i)/sqrt2 fwd; conj for inv
template <int CONJ> __device__ __forceinline__ cpx mul_w83(cpx a) {
    return CONJ ? cpx{-C_SQ * (a.x + a.y), C_SQ * (a.x - a.y)}
                : cpx{C_SQ * (a.y - a.x), -C_SQ * (a.x + a.y)};
}

// radix-8 DIF butterfly; outputs bit-reversed: y_r = a[brev(r)], brev = 0,4,2,6,1,5,3,7
template <int CONJ> __device__ __forceinline__ void dft8(cpx a[8]) {
    fft2p(a[0], a[4]); fft2p(a[1], a[5]); fft2p(a[2], a[6]); fft2p(a[3], a[7]);
    a[5] = mul_w81<CONJ>(a[5]);
    a[6] = mul_mi<CONJ>(a[6]);
    a[7] = mul_w83<CONJ>(a[7]);
    fft2p(a[0], a[2]); fft2p(a[1], a[3]);
    a[3] = mul_mi<CONJ>(a[3]);
    fft2p(a[4], a[6]); fft2p(a[5], a[7]);
    a[7] = mul_mi<CONJ>(a[7]);
    fft2p(a[0], a[1]); fft2p(a[2], a[3]); fft2p(a[4], a[5]); fft2p(a[6], a[7]);
}
// radix-4 DIF; y_r = a[brev2(r)], brev2 = 0,2,1,3
template <int CONJ> __device__ __forceinline__ void dft4(cpx a[4]) {
    fft2p(a[0], a[2]); fft2p(a[1], a[3]);
    a[3] = mul_mi<CONJ>(a[3]);
    fft2p(a[0], a[1]); fft2p(a[2], a[3]);
}

__device__ __forceinline__ float2 tw_lookup_g(int idx) {
    if (idx <= 1024) return g_T[idx];
    float2 u = g_T[2048 - idx];
    return make_float2(-u.x, u.y);
}

// store helper: write y_r = a[brev(r)] * w^r into SoA shared at idx(r)
#define ST8(RE, IM, IDX0, STRIDE)                                              \
    do {                                                                       \
        cpx y;                                                                 \
        y = a[0];              RE[PADi((IDX0))] = y.x; IM[PADi((IDX0))] = y.y; \
        y = cmul(a[4], w1);    RE[PADi((IDX0) + (STRIDE))] = y.x; IM[PADi((IDX0) + (STRIDE))] = y.y; \
        y = cmul(a[2], w2);    RE[PADi((IDX0) + 2*(STRIDE))] = y.x; IM[PADi((IDX0) + 2*(STRIDE))] = y.y; \
        y = cmul(a[6], w3);    RE[PADi((IDX0) + 3*(STRIDE))] = y.x; IM[PADi((IDX0) + 3*(STRIDE))] = y.y; \
        y = cmul(a[1], w4);    RE[PADi((IDX0) + 4*(STRIDE))] = y.x; IM[PADi((IDX0) + 4*(STRIDE))] = y.y; \
        y = cmul(a[5], w5);    RE[PADi((IDX0) + 5*(STRIDE))] = y.x; IM[PADi((IDX0) + 5*(STRIDE))] = y.y; \
        y = cmul(a[3], w6);    RE[PADi((IDX0) + 6*(STRIDE))] = y.x; IM[PADi((IDX0) + 6*(STRIDE))] = y.y; \
        y = cmul(a[7], w7);    RE[PADi((IDX0) + 7*(STRIDE))] = y.x; IM[PADi((IDX0) + 7*(STRIDE))] = y.y; \
    } while (0)

#define MAKE_POWERS(base)                                                      \
    cpx w1 = base;                                                             \
    cpx w2 = cmul(w1, w1); cpx w3 = cmul(w2, w1); cpx w4 = cmul(w2, w2);       \
    cpx w5 = cmul(w4, w1); cpx w6 = cmul(w3, w3); cpx w7 = cmul(w4, w3)

// passes 1..3 operating on shared SoA; input already in B (after pass0)
template <int CONJ>
__device__ __forceinline__ void fft_passes_123(
    float* sRa, float* sIa, float* sRb, float* sIb, int t) {
    // pass1: B -> A   (s=8, P=32)
    {
        cpx a[8];
        #pragma unroll
        for (int r = 0; r < 8; r++) {
            int i = PADi(t + 256 * r);
            a[r] = cpx{sRb[i], sIb[i]};
        }
        dft8<CONJ>(a);
        int p = t >> 3, q = t & 7;
        float2 wb = g_T[16 * p];
        cpx base{wb.x, CONJ ? -wb.y : wb.y};
        MAKE_POWERS(base);
        int i0 = q + 64 * p;
        ST8(sRa, sIa, i0, 8);
    }
    __syncthreads();
    // pass2: A -> B   (s=64, P=4)
    {
        cpx a[8];
        int q = t & 63, p = t >> 6;
        #pragma unroll
        for (int r = 0; r < 8; r++) {
            int i = PADi(q + 64 * p + 256 * r);
            a[r] = cpx{sRa[i], sIa[i]};
        }
        dft8<CONJ>(a);
        float2 wb = g_T[128 * p];
        cpx base{wb.x, CONJ ? -wb.y : wb.y};
        MAKE_POWERS(base);
        int i0 = q + 512 * p;
        ST8(sRb, sIb, i0, 64);
    }
    __syncthreads();
}

// ---------------- K-1: twiddle table ----------------
__global__ void k_init_tw() {
    int k = blockIdx.x * 256 + threadIdx.x;
    if (k <= 1024) {
        float s, c;
        sincosf(CUDART_PI_F * (float)k / 2048.f, &s, &c);
        g_T[k] = make_float2(c, -s);
    }
}

// ---------------- K0: band boundaries -> per-bin expert index ----------------
__global__ void k_band(const float* __restrict__ bb) {
    __shared__ int idx[9];
    if (threadIdx.x == 0) {
        float v[7];
        #pragma unroll
        for (int i = 0; i < 7; i++) v[i] = 1.f / (1.f + expf(-bb[i]));
        for (int i = 1; i < 7; i++) {
            float key = v[i]; int j = i - 1;
            while (j >= 0 && v[j] > key) { v[j + 1] = v[j]; j--; }
            v[j + 1] = key;
        }
        idx[0] = 0;
        for (int e = 1; e < 8; e++) {
            int t = (int)(v[e - 1] * 2049.0f);
            idx[e] = min(max(t, 0), 2049);
        }
        idx[8] = 2049;
    }
    __syncthreads();
    for (int f = threadIdx.x; f < Fn; f += blockDim.x) {
        int e = 0;
        #pragma unroll
        for (int t = 0; t < 8; t++)
            if (f >= idx[t] && f < idx[t + 1]) { e = t; break; }
        g_bandOf[f] = e;
    }
}

// ---------------- K1: transpose x [B,L,N] -> g_xt [B,N,L] (float4) ----------------
__global__ void k_transpose_in(const float* __restrict__ x) {
    __shared__ float tile[32][33];
    int b = blockIdx.z;
    int l0 = blockIdx.x * 32, n0 = blockIdx.y * 32;
    int tx = threadIdx.x, ty = threadIdx.y;  // 8 x 32
    const float4* x4 = (const float4*)x;
    float4 v = x4[(((size_t)(b * Ln + l0 + ty)) * Nn + n0 + 4 * tx) >> 2];
    tile[ty][4 * tx + 0] = v.x;
    tile[ty][4 * tx + 1] = v.y;
    tile[ty][4 * tx + 2] = v.z;
    tile[ty][4 * tx + 3] = v.w;
    __syncthreads();
    float4 w;
    w.x = tile[4 * tx + 0][ty];
    w.y = tile[4 * tx + 1][ty];
    w.z = tile[4 * tx + 2][ty];
    w.w = tile[4 * tx + 3][ty];
    float4* o4 = (float4*)g_xt;
    o4[(((size_t)(b * Nn + n0 + ty)) * Ln + l0 + 4 * tx) >> 2] = w;
}

// ---------------- K2: per-series mean/var + rfft ----------------
__global__ __launch_bounds__(256) void k_fwd() {
    __shared__ float sRa[2304], sIa[2304], sRb[2304], sIb[2304];
    __shared__ float sred[16];
    int series = blockIdx.x;
    int t = threadIdx.x;
    const float2* row = (const float2*)(g_xt + (size_t)series * Ln);

    // load 8 elements (t + 256r) + mean/var partials
    cpx a[8];
    float s1 = 0.f, s2 = 0.f;
    #pragma unroll
    for (int r = 0; r < 8; r++) {
        float2 v = row[t + 256 * r];
        a[r] = cpx{v.x, v.y};
        s1 += v.x + v.y;
        s2 += v.x * v.x + v.y * v.y;
    }
    #pragma unroll
    for (int off = 16; off; off >>= 1) {
        s1 += __shfl_down_sync(~0u, s1, off);
        s2 += __shfl_down_sync(~0u, s2, off);
    }
    if ((t & 31) == 0) { sred[t >> 5] = s1; sred[8 + (t >> 5)] = s2; }

    // pass0: regs -> B  (s=1, P=256), twiddle W_2048^t
    dft8<0>(a);
    {
        float2 wb = g_T[2 * t];
        cpx base{wb.x, wb.y};
        MAKE_POWERS(base);
        ST8(sRb, sIb, 8 * t, 1);
    }
    __syncthreads();
    if (t == 0) {
        float aa = 0.f, bb = 0.f;
        #pragma unroll
        for (int w = 0; w < 8; w++) { aa += sred[w]; bb += sred[8 + w]; }
        float mean = aa * (1.f / 4096.f);
        float var = bb * (1.f / 4096.f) - mean * mean + 1e-6f;
        g_mean[series] = mean;
        g_std[series]  = sqrtf(fmaxf(var, 0.f));
    }

    fft_passes_123<0>(sRa, sIa, sRb, sIb, t);

    // pass3: radix-4, B -> A  (s=512)
    #pragma unroll
    for (int uu = 0; uu < 2; uu++) {
        int u = t + 256 * uu;
        cpx c4[4];
        #pragma unroll
        for (int r = 0; r < 4; r++) {
            int i = PADi(u + 512 * r);
            c4[r] = cpx{sRb[i], sIb[i]};
        }
        dft4<0>(c4);
        sRa[PADi(u)]        = c4[0].x; sIa[PADi(u)]        = c4[0].y;
        sRa[PADi(u + 512)]  = c4[2].x; sIa[PADi(u + 512)]  = c4[2].y;
        sRa[PADi(u + 1024)] = c4[1].x; sIa[PADi(u + 1024)] = c4[1].y;
        sRa[PADi(u + 1536)] = c4[3].x; sIa[PADi(u + 1536)] = c4[3].y;
    }
    __syncthreads();

    // untangle packed FFT -> rfft bins
    float2* out = g_freq + (size_t)series * Fn;
    for (int k = t; k < Fn; k += 256) {
        int ik = PADi(k & (N2h - 1));
        int imk = PADi((N2h - k) & (N2h - 1));
        cpx zk{sRa[ik], sIa[ik]};
        cpx zmk{sRa[imk], sIa[imk]};
        float2 A = make_float2(0.5f * (zk.x + zmk.x), 0.5f * (zk.y - zmk.y));
        float dx = zk.x - zmk.x, dy = zk.y + zmk.y;
        float2 Bv = make_float2(0.5f * dy, -0.5f * dx);
        float2 tw = tw_lookup_g(k);
        out[k] = make_float2(A.x + tw.x * Bv.x - tw.y * Bv.y,
                             A.y + tw.x * Bv.y + tw.y * Bv.x);
    }
}

// ---------------- K3: mag ----------------
__global__ __launch_bounds__(256) void k_mag() {
    int f = blockIdx.x * 256 + threadIdx.x;
    int b = blockIdx.y;
    if (f >= Fn) return;
    const float2* base = g_freq + (size_t)b * Nn * Fn + f;
    float acc[8];
    #pragma unroll
    for (int j = 0; j < 8; j++) acc[j] = 0.f;
    #pragma unroll 2
    for (int n0 = 0; n0 < Nn; n0 += 8) {
        #pragma unroll
        for (int j = 0; j < 8; j++) {
            float2 v = base[(size_t)(n0 + j) * Fn];
            acc[j] += sqrtf(v.x * v.x + v.y * v.y);
        }
    }
    float s = ((acc[0] + acc[1]) + (acc[2] + acc[3])) +
              ((acc[4] + acc[5]) + (acc[6] + acc[7]));
    g_mag[b * Fn + f] = s * (1.f / 128.f);
}

// ---------------- K4: h = relu(mag @ W1 + b1) ----------------
__global__ __launch_bounds__(256) void k_gemm1(const float* __restrict__ w1,
                                               const float* __restrict__ b1) {
    __shared__ float sMag[64 * 32];
    __shared__ float sW[32 * 33];
    int j0 = blockIdx.x * 32;
    int tid = threadIdx.x;
    int tj = tid & 31, tr = tid >> 5;
    float acc[8];
    #pragma unroll
    for (int r = 0; r < 8; r++) acc[r] = 0.f;

    for (int k0 = 0; k0 < Fn; k0 += 32) {
        for (int t = tid; t < 2048; t += 256) {
            int bb = t >> 5, kk = t & 31;
            int k = k0 + kk;
            sMag[t] = (k < Fn) ? g_mag[bb * Fn + k] : 0.f;
        }
        for (int t = tid; t < 1024; t += 256) {
            int kk = t >> 5, j = t & 31;
            int k = k0 + kk, jj = j0 + j;
            sW[kk * 33 + j] = (k < Fn && jj < Fn) ? w1[(size_t)k * Fn + jj] : 0.f;
        }
        __syncthreads();
        #pragma unroll
        for (int kk = 0; kk < 32; kk++) {
            float wv = sW[kk * 33 + tj];
            #pragma unroll
            for (int r = 0; r < 8; r++)
                acc[r] = fmaf(sMag[(tr + 8 * r) * 32 + kk], wv, acc[r]);
        }
        __syncthreads();
    }
    int j = j0 + tj;
    if (j < Fn) {
        float bias = b1[j];
        #pragma unroll
        for (int r = 0; r < 8; r++) {
            int bb = tr + 8 * r;
            g_h[bb * Fn + j] = fmaxf(acc[r] + bias, 0.f);
        }
    }
}

// ---------------- K5: logits -> softmax -> wmask ----------------
__global__ __launch_bounds__(256) void k_gate2(const float* __restrict__ w2,
                                               const float* __restrict__ b2) {
    __shared__ float slog[8];
    __shared__ float sw[8];
    int b = blockIdx.x;
    int tid = threadIdx.x, warp = tid >> 5, lane = tid & 31;
    float part = 0.f;
    for (int k = lane; k < Fn; k += 32)
        part += g_h[b * Fn + k] * w2[k * En + warp];
    #pragma unroll
    for (int off = 16; off; off >>= 1) part += __shfl_down_sync(~0u, part, off);
    if (lane == 0) slog[warp] = part + b2[warp];
    __syncthreads();
    if (tid == 0) {
        float mx = -1e30f;
        for (int e = 0; e < 8; e++) mx = fmaxf(mx, slog[e]);
        float s = 0.f, ex[8];
        for (int e = 0; e < 8; e++) { ex[e] = expf(slog[e] - mx); s += ex[e]; }
        float inv = 1.f / s;
        for (int e = 0; e < 8; e++) sw[e] = ex[e] * inv;
    }
    __syncthreads();
    for (int f = tid; f < Fn; f += 256)
        g_wmask[b * Fn + f] = sw[g_bandOf[f]];
}

// ---------------- K6: filter + irfft -> g_xt ----------------
__global__ __launch_bounds__(256) void k_inv() {
    __shared__ float sRa[2304], sIa[2304], sRb[2304], sIb[2304];
    __shared__ float2 sX2048;
    int series = blockIdx.x;
    int b = series >> 7;
    int t = threadIdx.x;
    const float2* Xg = g_freq + (size_t)series * Fn;
    const float*  wm = g_wmask + b * Fn;

    // stage X * wmask into A (natural index, padded)
    for (int k = t; k < 2048; k += 256) {
        float2 v = Xg[k];
        float w = wm[k];
        int i = PADi(k);
        sRa[i] = v.x * w;
        sIa[i] = v.y * w;
    }
    if (t == 0) {
        float2 v = Xg[2048];
        float w = wm[2048];
        sX2048 = make_float2(v.x * w, v.y * w);
    }
    __syncthreads();

    // repack rfft bins -> Z[0..2047] in place
    for (int k = t; k <= 1024; k += 256) {
        int ik = PADi(k), imk = PADi(2048 - k);
        cpx Xk{sRa[ik], sIa[ik]};
        cpx Xmk = (k == 0) ? cpx{sX2048.x, sX2048.y} : cpx{sRa[imk], sIa[imk]};
        float2 A = make_float2(0.5f * (Xk.x + Xmk.x), 0.5f * (Xk.y - Xmk.y));
        float dx = Xk.x - Xmk.x, dy = Xk.y + Xmk.y;
        float2 tw = g_T[k];          // (cos, -sin)
        float c = tw.x, sn = -tw.y;
        float2 Bc = make_float2(0.5f * (c * dx - sn * dy), 0.5f * (c * dy + sn * dx));
        sRa[ik] = A.x - Bc.y;
        sIa[ik] = A.y + Bc.x;
        if (k >= 1 && k < 1024) {
            sRa[imk] = A.x + Bc.y;
            sIa[imk] = Bc.x - A.y;
        }
    }
    __syncthreads();

    // pass0: A -> B (inverse twiddles)
    {
        cpx a[8];
        #pragma unroll
        for (int r = 0; r < 8; r++) {
            int i = PADi(t + 256 * r);
            a[r] = cpx{sRa[i], sIa[i]};
        }
        dft8<1>(a);
        float2 wb = g_T[2 * t];
        cpx base{wb.x, -wb.y};
        MAKE_POWERS(base);
        ST8(sRb, sIb, 8 * t, 1);
    }
    __syncthreads();

    fft_passes_123<1>(sRa, sIa, sRb, sIb, t);

    // pass3: radix-4, B -> global (scale + mean)
    float2* outrow = (float2*)(g_xt + (size_t)series * Ln);
    float mean = g_mean[series];
    float stdv = g_std[series] * (1.f / 2048.f);
    #pragma unroll
    for (int uu = 0; uu < 2; uu++) {
        int u = t + 256 * uu;
        cpx c4[4];
        #pragma unroll
        for (int r = 0; r < 4; r++) {
            int i = PADi(u + 512 * r);
            c4[r] = cpx{sRb[i], sIb[i]};
        }
        dft4<1>(c4);
        outrow[u]        = make_float2(fmaf(c4[0].x, stdv, mean), fmaf(c4[0].y, stdv, mean));
        outrow[u + 512]  = make_float2(fmaf(c4[2].x, stdv, mean), fmaf(c4[2].y, stdv, mean));
        outrow[u + 1024] = make_float2(fmaf(c4[1].x, stdv, mean), fmaf(c4[1].y, stdv, mean));
        outrow[u + 1536] = make_float2(fmaf(c4[3].x, stdv, mean), fmaf(c4[3].y, stdv, mean));
    }
}

// ---------------- K7: out[b,l,n] = x[b,l,n] + rec[b,n,l] (float4) ----------------
__global__ void k_transpose_out(const float* __restrict__ x, float* __restrict__ out) {
    __shared__ float tile[32][33];
    int b = blockIdx.z;
    int l0 = blockIdx.x * 32, n0 = blockIdx.y * 32;
    int tx = threadIdx.x, ty = threadIdx.y;  // 8 x 32
    const float4* g4 = (const float4*)g_xt;
    float4 v = g4[(((size_t)(b * Nn + n0 + ty)) * Ln + l0 + 4 * tx) >> 2];
    tile[ty][4 * tx + 0] = v.x;
    tile[ty][4 * tx + 1] = v.y;
    tile[ty][4 * tx + 2] = v.z;
    tile[ty][4 * tx + 3] = v.w;
    __syncthreads();
    size_t idx = (((size_t)(b * Ln + l0 + ty)) * Nn + n0 + 4 * tx) >> 2;
    float4 xo = ((const float4*)x)[idx];
    float4 w;
    w.x = xo.x + tile[4 * tx + 0][ty];
    w.y = xo.y + tile[4 * tx + 1][ty];
    w.z = xo.z + tile[4 * tx + 2][ty];
    w.w = xo.w + tile[4 * tx + 3][ty];
    ((float4*)out)[idx] = w;
}

extern "C" void kernel_launch(void* const* d_in, const int* in_sizes, int n_in,
                              void* d_out, int out_size) {
    const float* x  = (const float*)d_in[0];
    const float* bb = (const float*)d_in[1];
    const float* w1 = (const float*)d_in[2];
    const float* b1 = (const float*)d_in[3];
    const float* w2 = (const float*)d_in[4];
    const float* b2 = (const float*)d_in[5];
    float* out = (float*)d_out;

    dim3 tb(8, 32);
    k_init_tw<<<5, 256>>>();
    k_band<<<1, 256>>>(bb);
    k_transpose_in<<<dim3(128, 4, 64), tb>>>(x);
    k_fwd<<<NSER, 256>>>();
    k_mag<<<dim3(9, 64), 256>>>();
    k_gemm1<<<65, 256>>>(w1, b1);
    k_gate2<<<64, 256>>>(w2, b2);
    k_inv<<<NSER, 256>>>();
    k_transpose_out<<<dim3(128, 4, 64), tb>>>(x, out);
}

// round 5
// speedup vs baseline: 2.0595x; 1.3393x over previous
#include <cuda_runtime.h>
#include <math_constants.h>

#define Bn 64
#define Ln 4096
#define Nn 128
#define Fn 2049
#define FS 2056          // padded row stride for g_freq (float2 units)
#define N2h 2048
#define En 8
#define NSER (Bn * Nn)   // 8192
#define KSPLIT 8
#define KCH 257          // 8*257 = 2056 >= 2049

#define C_SQ 0.70710678118654752f
#define PADi(i) ((i) + ((i) >> 3))

// ---------------- scratch ----------------
__device__ float  g_xt[(size_t)NSER * Ln];
__device__ float2 g_freq[(size_t)NSER * FS];
__device__ float  g_mean[NSER];
__device__ float  g_std[NSER];
__device__ float  g_magT[Fn * 64];            // [f][b]
__device__ float  g_hp[KSPLIT * 64 * Fn];     // gemm partials [ks][b][j]
__device__ float  g_h[Bn * Fn];
__device__ float  g_wmask[Bn * Fn];
__device__ int    g_bandOf[Fn];
__device__ float2 g_T[1025];   // T[i] = exp(-i*pi*i/2048), i=0..1024

struct cpx { float x, y; };
__device__ __forceinline__ cpx cmul(cpx a, cpx b) {
    return cpx{a.x * b.x - a.y * b.y, a.x * b.y + a.y * b.x};
}
__device__ __forceinline__ void fft2p(cpx& a, cpx& b) {
    cpx t{a.x - b.x, a.y - b.y};
    a = cpx{a.x + b.x, a.y + b.y};
    b = t;
}
template <int CONJ> __device__ __forceinline__ cpx mul_mi(cpx a) {
    return CONJ ? cpx{-a.y, a.x} : cpx{a.y, -a.x};
}
template <int CONJ> __device__ __forceinline__ cpx mul_w81(cpx a) {
    return CONJ ? cpx{C_SQ * (a.x - a.y), C_SQ * (a.y + a.x)}
                : cpx{C_SQ * (a.x + a.y), C_SQ * (a.y - a.x)};
}
template <int CONJ> __device__ __forceinline__ cpx mul_w83(cpx a) {
    return CONJ ? cpx{-C_SQ * (a.x + a.y), C_SQ * (a.x - a.y)}
                : cpx{C_SQ * (a.y - a.x), -C_SQ * (a.x + a.y)};
}

// radix-8 DIF butterfly; outputs bit-reversed: y_r = a[brev(r)], brev = 0,4,2,6,1,5,3,7
template <int CONJ> __device__ __forceinline__ void dft8(cpx a[8]) {
    fft2p(a[0], a[4]); fft2p(a[1], a[5]); fft2p(a[2], a[6]); fft2p(a[3], a[7]);
    a[5] = mul_w81<CONJ>(a[5]);
    a[6] = mul_mi<CONJ>(a[6]);
    a[7] = mul_w83<CONJ>(a[7]);
    fft2p(a[0], a[2]); fft2p(a[1], a[3]);
    a[3] = mul_mi<CONJ>(a[3]);
    fft2p(a[4], a[6]); fft2p(a[5], a[7]);
    a[7] = mul_mi<CONJ>(a[7]);
    fft2p(a[0], a[1]); fft2p(a[2], a[3]); fft2p(a[4], a[5]); fft2p(a[6], a[7]);
}
template <int CONJ> __device__ __forceinline__ void dft4(cpx a[4]) {
    fft2p(a[0], a[2]); fft2p(a[1], a[3]);
    a[3] = mul_mi<CONJ>(a[3]);
    fft2p(a[0], a[1]); fft2p(a[2], a[3]);
}

__device__ __forceinline__ float2 tw_lookup_g(int idx) {
    if (idx <= 1024) return g_T[idx];
    float2 u = g_T[2048 - idx];
    return make_float2(-u.x, u.y);
}

#define ST8(RE, IM, IDX0, STRIDE)                                              \
    do {                                                                       \
        cpx y;                                                                 \
        y = a[0];              RE[PADi((IDX0))] = y.x; IM[PADi((IDX0))] = y.y; \
        y = cmul(a[4], w1);    RE[PADi((IDX0) + (STRIDE))] = y.x; IM[PADi((IDX0) + (STRIDE))] = y.y; \
        y = cmul(a[2], w2);    RE[PADi((IDX0) + 2*(STRIDE))] = y.x; IM[PADi((IDX0) + 2*(STRIDE))] = y.y; \
        y = cmul(a[6], w3);    RE[PADi((IDX0) + 3*(STRIDE))] = y.x; IM[PADi((IDX0) + 3*(STRIDE))] = y.y; \
        y = cmul(a[1], w4);    RE[PADi((IDX0) + 4*(STRIDE))] = y.x; IM[PADi((IDX0) + 4*(STRIDE))] = y.y; \
        y = cmul(a[5], w5);    RE[PADi((IDX0) + 5*(STRIDE))] = y.x; IM[PADi((IDX0) + 5*(STRIDE))] = y.y; \
        y = cmul(a[3], w6);    RE[PADi((IDX0) + 6*(STRIDE))] = y.x; IM[PADi((IDX0) + 6*(STRIDE))] = y.y; \
        y = cmul(a[7], w7);    RE[PADi((IDX0) + 7*(STRIDE))] = y.x; IM[PADi((IDX0) + 7*(STRIDE))] = y.y; \
    } while (0)

#define MAKE_POWERS(base)                                                      \
    cpx w1 = base;                                                             \
    cpx w2 = cmul(w1, w1); cpx w3 = cmul(w2, w1); cpx w4 = cmul(w2, w2);       \
    cpx w5 = cmul(w4, w1); cpx w6 = cmul(w3, w3); cpx w7 = cmul(w4, w3)

template <int CONJ>
__device__ __forceinline__ void fft_passes_123(
    float* sRa, float* sIa, float* sRb, float* sIb, int t) {
    // pass1: B -> A   (s=8)
    {
        cpx a[8];
        #pragma unroll
        for (int r = 0; r < 8; r++) {
            int i = PADi(t + 256 * r);
            a[r] = cpx{sRb[i], sIb[i]};
        }
        dft8<CONJ>(a);
        int p = t >> 3, q = t & 7;
        float2 wb = g_T[16 * p];
        cpx base{wb.x, CONJ ? -wb.y : wb.y};
        MAKE_POWERS(base);
        int i0 = q + 64 * p;
        ST8(sRa, sIa, i0, 8);
    }
    __syncthreads();
    // pass2: A -> B   (s=64)
    {
        cpx a[8];
        int q = t & 63, p = t >> 6;
        #pragma unroll
        for (int r = 0; r < 8; r++) {
            int i = PADi(q + 64 * p + 256 * r);
            a[r] = cpx{sRa[i], sIa[i]};
        }
        dft8<CONJ>(a);
        float2 wb = g_T[128 * p];
        cpx base{wb.x, CONJ ? -wb.y : wb.y};
        MAKE_POWERS(base);
        int i0 = q + 512 * p;
        ST8(sRb, sIb, i0, 64);
    }
    __syncthreads();
}

// ---------------- K0: twiddle table + band indices (merged) ----------------
__global__ void k_init(const float* __restrict__ bb) {
    int k = blockIdx.x * 256 + threadIdx.x;
    if (k <= 1024) {
        float s, c;
        sincosf(CUDART_PI_F * (float)k / 2048.f, &s, &c);
        g_T[k] = make_float2(c, -s);
    }
    if (blockIdx.x == 0) {
        __shared__ int idx[9];
        if (threadIdx.x == 0) {
            float v[7];
            #pragma unroll
            for (int i = 0; i < 7; i++) v[i] = 1.f / (1.f + expf(-bb[i]));
            for (int i = 1; i < 7; i++) {
                float key = v[i]; int j = i - 1;
                while (j >= 0 && v[j] > key) { v[j + 1] = v[j]; j--; }
                v[j + 1] = key;
            }
            idx[0] = 0;
            for (int e = 1; e < 8; e++) {
                int t = (int)(v[e - 1] * 2049.0f);
                idx[e] = min(max(t, 0), 2049);
            }
            idx[8] = 2049;
        }
        __syncthreads();
        for (int f = threadIdx.x; f < Fn; f += 256) {
            int e = 0;
            #pragma unroll
            for (int t = 0; t < 8; t++)
                if (f >= idx[t] && f < idx[t + 1]) { e = t; break; }
            g_bandOf[f] = e;
        }
    }
}

// ---------------- K1: transpose x [B,L,N] -> g_xt [B,N,L] ----------------
__global__ void k_transpose_in(const float* __restrict__ x) {
    __shared__ float tile[32][33];
    int b = blockIdx.z;
    int l0 = blockIdx.x * 32, n0 = blockIdx.y * 32;
    int tx = threadIdx.x, ty = threadIdx.y;  // 8 x 32
    const float4* x4 = (const float4*)x;
    float4 v = x4[(((size_t)(b * Ln + l0 + ty)) * Nn + n0 + 4 * tx) >> 2];
    tile[ty][4 * tx + 0] = v.x;
    tile[ty][4 * tx + 1] = v.y;
    tile[ty][4 * tx + 2] = v.z;
    tile[ty][4 * tx + 3] = v.w;
    __syncthreads();
    float4 w;
    w.x = tile[4 * tx + 0][ty];
    w.y = tile[4 * tx + 1][ty];
    w.z = tile[4 * tx + 2][ty];
    w.w = tile[4 * tx + 3][ty];
    float4* o4 = (float4*)g_xt;
    o4[(((size_t)(b * Nn + n0 + ty)) * Ln + l0 + 4 * tx) >> 2] = w;
}

// ---------------- K2: per-series mean/var + rfft ----------------
__global__ __launch_bounds__(256) void k_fwd() {
    __shared__ float sRa[2304], sIa[2304], sRb[2304], sIb[2304];
    __shared__ float sred[16];
    int series = blockIdx.x;
    int t = threadIdx.x;
    const float2* row = (const float2*)(g_xt + (size_t)series * Ln);

    cpx a[8];
    float s1 = 0.f, s2 = 0.f;
    #pragma unroll
    for (int r = 0; r < 8; r++) {
        float2 v = row[t + 256 * r];
        a[r] = cpx{v.x, v.y};
        s1 += v.x + v.y;
        s2 += v.x * v.x + v.y * v.y;
    }
    #pragma unroll
    for (int off = 16; off; off >>= 1) {
        s1 += __shfl_down_sync(~0u, s1, off);
        s2 += __shfl_down_sync(~0u, s2, off);
    }
    if ((t & 31) == 0) { sred[t >> 5] = s1; sred[8 + (t >> 5)] = s2; }

    dft8<0>(a);
    {
        float2 wb = g_T[2 * t];
        cpx base{wb.x, wb.y};
        MAKE_POWERS(base);
        ST8(sRb, sIb, 8 * t, 1);
    }
    __syncthreads();
    if (t == 0) {
        float aa = 0.f, bb = 0.f;
        #pragma unroll
        for (int w = 0; w < 8; w++) { aa += sred[w]; bb += sred[8 + w]; }
        float mean = aa * (1.f / 4096.f);
        float var = bb * (1.f / 4096.f) - mean * mean + 1e-6f;
        g_mean[series] = mean;
        g_std[series]  = sqrtf(fmaxf(var, 0.f));
    }

    fft_passes_123<0>(sRa, sIa, sRb, sIb, t);

    // pass3: radix-4, B -> A
    #pragma unroll
    for (int uu = 0; uu < 2; uu++) {
        int u = t + 256 * uu;
        cpx c4[4];
        #pragma unroll
        for (int r = 0; r < 4; r++) {
            int i = PADi(u + 512 * r);
            c4[r] = cpx{sRb[i], sIb[i]};
        }
        dft4<0>(c4);
        sRa[PADi(u)]        = c4[0].x; sIa[PADi(u)]        = c4[0].y;
        sRa[PADi(u + 512)]  = c4[2].x; sIa[PADi(u + 512)]  = c4[2].y;
        sRa[PADi(u + 1024)] = c4[1].x; sIa[PADi(u + 1024)] = c4[1].y;
        sRa[PADi(u + 1536)] = c4[3].x; sIa[PADi(u + 1536)] = c4[3].y;
    }
    __syncthreads();

    // untangle packed FFT -> rfft bins
    float2* out = g_freq + (size_t)series * FS;
    for (int k = t; k < Fn; k += 256) {
        int ik = PADi(k & (N2h - 1));
        int imk = PADi((N2h - k) & (N2h - 1));
        cpx zk{sRa[ik], sIa[ik]};
        cpx zmk{sRa[imk], sIa[imk]};
        float2 A = make_float2(0.5f * (zk.x + zmk.x), 0.5f * (zk.y - zmk.y));
        float dx = zk.x - zmk.x, dy = zk.y + zmk.y;
        float2 Bv = make_float2(0.5f * dy, -0.5f * dx);
        float2 tw = tw_lookup_g(k);
        out[k] = make_float2(A.x + tw.x * Bv.x - tw.y * Bv.y,
                             A.y + tw.x * Bv.y + tw.y * Bv.x);
    }
}

// ---------------- K3: magT[f][b] = mean_n |freq[b,n,f]| ----------------
__global__ __launch_bounds__(256) void k_mag() {
    int f = blockIdx.x * 256 + threadIdx.x;
    int b = blockIdx.y;
    if (f >= Fn) return;
    const float2* base = g_freq + (size_t)b * Nn * FS + f;
    float acc[8];
    #pragma unroll
    for (int j = 0; j < 8; j++) acc[j] = 0.f;
    #pragma unroll 2
    for (int n0 = 0; n0 < Nn; n0 += 8) {
        #pragma unroll
        for (int j = 0; j < 8; j++) {
            float2 v = base[(size_t)(n0 + j) * FS];
            acc[j] += sqrtf(v.x * v.x + v.y * v.y);
        }
    }
    float s = ((acc[0] + acc[1]) + (acc[2] + acc[3])) +
              ((acc[4] + acc[5]) + (acc[6] + acc[7]));
    g_magT[f * 64 + b] = s * (1.f / 128.f);
}

// ---------------- K4a: GEMM partials, K-split. block = 64 j x 4 bgroups ----------------
__global__ __launch_bounds__(256) void k_gemm1a(const float* __restrict__ w1) {
    int tid = threadIdx.x;
    int j = blockIdx.x * 64 + (tid & 63);
    int bg = tid >> 6;                // 0..3 -> rows 16*bg..16*bg+15
    int ks = blockIdx.y;
    int kbeg = ks * KCH;
    int kend = min(kbeg + KCH, Fn);
    bool jok = (j < Fn);

    float acc[16];
    #pragma unroll
    for (int i = 0; i < 16; i++) acc[i] = 0.f;

    const float4* magT4 = (const float4*)g_magT;
    #pragma unroll 2
    for (int k = kbeg; k < kend; k++) {
        float wv = jok ? __ldg(&w1[(size_t)k * Fn + j]) : 0.f;
        const float4* mrow = magT4 + ((size_t)k << 4) + (bg << 2);
        float4 m0 = mrow[0], m1 = mrow[1], m2 = mrow[2], m3 = mrow[3];
        acc[0]  = fmaf(m0.x, wv, acc[0]);  acc[1]  = fmaf(m0.y, wv, acc[1]);
        acc[2]  = fmaf(m0.z, wv, acc[2]);  acc[3]  = fmaf(m0.w, wv, acc[3]);
        acc[4]  = fmaf(m1.x, wv, acc[4]);  acc[5]  = fmaf(m1.y, wv, acc[5]);
        acc[6]  = fmaf(m1.z, wv, acc[6]);  acc[7]  = fmaf(m1.w, wv, acc[7]);
        acc[8]  = fmaf(m2.x, wv, acc[8]);  acc[9]  = fmaf(m2.y, wv, acc[9]);
        acc[10] = fmaf(m2.z, wv, acc[10]); acc[11] = fmaf(m2.w, wv, acc[11]);
        acc[12] = fmaf(m3.x, wv, acc[12]); acc[13] = fmaf(m3.y, wv, acc[13]);
        acc[14] = fmaf(m3.z, wv, acc[14]); acc[15] = fmaf(m3.w, wv, acc[15]);
    }
    if (jok) {
        #pragma unroll
        for (int i = 0; i < 16; i++) {
            int b = 16 * bg + i;
            g_hp[((size_t)(ks * 64 + b)) * Fn + j] = acc[i];
        }
    }
}

// ---------------- K4b: reduce partials + bias + relu -> g_h ----------------
__global__ __launch_bounds__(256) void k_gemm1b(const float* __restrict__ b1) {
    int j = blockIdx.x * 256 + threadIdx.x;
    int b = blockIdx.y;
    if (j >= Fn) return;
    float s = 0.f;
    #pragma unroll
    for (int ks = 0; ks < KSPLIT; ks++)
        s += g_hp[((size_t)(ks * 64 + b)) * Fn + j];
    g_h[b * Fn + j] = fmaxf(s + b1[j], 0.f);
}

// ---------------- K5: logits -> softmax -> wmask ----------------
__global__ __launch_bounds__(256) void k_gate2(const float* __restrict__ w2,
                                               const float* __restrict__ b2) {
    __shared__ float slog[8];
    __shared__ float sw[8];
    int b = blockIdx.x;
    int tid = threadIdx.x, warp = tid >> 5, lane = tid & 31;
    float part = 0.f;
    for (int k = lane; k < Fn; k += 32)
        part += g_h[b * Fn + k] * w2[k * En + warp];
    #pragma unroll
    for (int off = 16; off; off >>= 1) part += __shfl_down_sync(~0u, part, off);
    if (lane == 0) slog[warp] = part + b2[warp];
    __syncthreads();
    if (tid == 0) {
        float mx = -1e30f;
        for (int e = 0; e < 8; e++) mx = fmaxf(mx, slog[e]);
        float s = 0.f, ex[8];
        for (int e = 0; e < 8; e++) { ex[e] = expf(slog[e] - mx); s += ex[e]; }
        float inv = 1.f / s;
        for (int e = 0; e < 8; e++) sw[e] = ex[e] * inv;
    }
    __syncthreads();
    for (int f = tid; f < Fn; f += 256)
        g_wmask[b * Fn + f] = sw[g_bandOf[f]];
}

// ---------------- K6: filter + irfft -> g_xt ----------------
__global__ __launch_bounds__(256) void k_inv() {
    __shared__ float sRa[2304], sIa[2304], sRb[2304], sIb[2304];
    int series = blockIdx.x;
    int b = series >> 7;
    int t = threadIdx.x;
    const float2* Xg = g_freq + (size_t)series * FS;
    const float*  wm = g_wmask + b * Fn;

    // fused filter + repack: rfft bins -> Z[0..2047] directly into sA
    for (int k = t; k <= 1024; k += 256) {
        float2 vk = Xg[k];
        float wk = wm[k];
        cpx Xk{vk.x * wk, vk.y * wk};
        int km = 2048 - k;
        float2 vm = Xg[km];
        float wmk = wm[km];
        cpx Xmk{vm.x * wmk, vm.y * wmk};
        float2 A = make_float2(0.5f * (Xk.x + Xmk.x), 0.5f * (Xk.y - Xmk.y));
        float dx = Xk.x - Xmk.x, dy = Xk.y + Xmk.y;
        float2 tw = g_T[k];          // (cos, -sin)
        float c = tw.x, sn = -tw.y;
        float2 Bc = make_float2(0.5f * (c * dx - sn * dy), 0.5f * (c * dy + sn * dx));
        int ik = PADi(k);
        sRa[ik] = A.x - Bc.y;
        sIa[ik] = A.y + Bc.x;
        if (k >= 1 && k < 1024) {
            int imk = PADi(2048 - k);
            sRa[imk] = A.x + Bc.y;
            sIa[imk] = Bc.x - A.y;
        }
    }
    __syncthreads();

    // pass0: A -> B (inverse twiddles)
    {
        cpx a[8];
        #pragma unroll
        for (int r = 0; r < 8; r++) {
            int i = PADi(t + 256 * r);
            a[r] = cpx{sRa[i], sIa[i]};
        }
        dft8<1>(a);
        float2 wb = g_T[2 * t];
        cpx base{wb.x, -wb.y};
        MAKE_POWERS(base);
        ST8(sRb, sIb, 8 * t, 1);
    }
    __syncthreads();

    fft_passes_123<1>(sRa, sIa, sRb, sIb, t);

    // pass3: radix-4, B -> global (scale + mean)
    float2* outrow = (float2*)(g_xt + (size_t)series * Ln);
    float mean = g_mean[series];
    float stdv = g_std[series] * (1.f / 2048.f);
    #pragma unroll
    for (int uu = 0; uu < 2; uu++) {
        int u = t + 256 * uu;
        cpx c4[4];
        #pragma unroll
        for (int r = 0; r < 4; r++) {
            int i = PADi(u + 512 * r);
            c4[r] = cpx{sRb[i], sIb[i]};
        }
        dft4<1>(c4);
        outrow[u]        = make_float2(fmaf(c4[0].x, stdv, mean), fmaf(c4[0].y, stdv, mean));
        outrow[u + 512]  = make_float2(fmaf(c4[2].x, stdv, mean), fmaf(c4[2].y, stdv, mean));
        outrow[u + 1024] = make_float2(fmaf(c4[1].x, stdv, mean), fmaf(c4[1].y, stdv, mean));
        outrow[u + 1536] = make_float2(fmaf(c4[3].x, stdv, mean), fmaf(c4[3].y, stdv, mean));
    }
}

// ---------------- K7: out[b,l,n] = x[b,l,n] + rec[b,n,l] ----------------
__global__ void k_transpose_out(const float* __restrict__ x, float* __restrict__ out) {
    __shared__ float tile[32][33];
    int b = blockIdx.z;
    int l0 = blockIdx.x * 32, n0 = blockIdx.y * 32;
    int tx = threadIdx.x, ty = threadIdx.y;  // 8 x 32
    const float4* g4 = (const float4*)g_xt;
    float4 v = g4[(((size_t)(b * Nn + n0 + ty)) * Ln + l0 + 4 * tx) >> 2];
    tile[ty][4 * tx + 0] = v.x;
    tile[ty][4 * tx + 1] = v.y;
    tile[ty][4 * tx + 2] = v.z;
    tile[ty][4 * tx + 3] = v.w;
    __syncthreads();
    size_t idx = (((size_t)(b * Ln + l0 + ty)) * Nn + n0 + 4 * tx) >> 2;
    float4 xo = ((const float4*)x)[idx];
    float4 w;
    w.x = xo.x + tile[4 * tx + 0][ty];
    w.y = xo.y + tile[4 * tx + 1][ty];
    w.z = xo.z + tile[4 * tx + 2][ty];
    w.w = xo.w + tile[4 * tx + 3][ty];
    ((float4*)out)[idx] = w;
}

extern "C" void kernel_launch(void* const* d_in, const int* in_sizes, int n_in,
                              void* d_out, int out_size) {
    const float* x  = (const float*)d_in[0];
    const float* bb = (const float*)d_in[1];
    const float* w1 = (const float*)d_in[2];
    const float* b1 = (const float*)d_in[3];
    const float* w2 = (const float*)d_in[4];
    const float* b2 = (const float*)d_in[5];
    float* out = (float*)d_out;

    dim3 tb(8, 32);
    k_init<<<5, 256>>>(bb);
    k_transpose_in<<<dim3(128, 4, 64), tb>>>(x);
    k_fwd<<<NSER, 256>>>();
    k_mag<<<dim3(9, 64), 256>>>();
    k_gemm1a<<<dim3(33, KSPLIT), 256>>>(w1);
    k_gemm1b<<<dim3(9, 64), 256>>>(b1);
    k_gate2<<<64, 256>>>(w2, b2);
    k_inv<<<NSER, 256>>>();
    k_transpose_out<<<dim3(128, 4, 64), tb>>>(x, out);
}

// round 6
// speedup vs baseline: 2.2510x; 1.0930x over previous
#include <cuda_runtime.h>
#include <cuda_fp16.h>
#include <math_constants.h>

#define Bn 64
#define Ln 4096
#define Nn 128
#define Fn 2049
#define FS 2056          // padded row stride for g_freq (bins)
#define N2h 2048
#define En 8
#define NSER (Bn * Nn)   // 8192
#define KSPLIT 8
#define KCH 257          // 8*257 = 2056 >= 2049

#define C_SQ 0.70710678118654752f
#define PADi(i) ((i) + ((i) >> 3))

// ---------------- scratch ----------------
__device__ float   g_xt[(size_t)NSER * Ln];
__device__ __half2 g_freq[(size_t)NSER * FS];   // fp16 spectrum (re,im)
__device__ float   g_mean[NSER];
__device__ float   g_std[NSER];
__device__ float   g_magp[2][Fn * 64];          // n-split partials [half][f*64+b]
__device__ float   g_magT[Fn * 64];             // [f][b]
__device__ float   g_hp[KSPLIT * 64 * Fn];      // gemm partials [ks][b][j]
__device__ float   g_h[Bn * Fn];
__device__ float   g_wmask[Bn * Fn];
__device__ int     g_bandOf[Fn];
__device__ float2  g_T[1025];   // T[i] = exp(-i*pi*i/2048), i=0..1024

struct cpx { float x, y; };
__device__ __forceinline__ cpx cmul(cpx a, cpx b) {
    return cpx{a.x * b.x - a.y * b.y, a.x * b.y + a.y * b.x};
}
__device__ __forceinline__ void fft2p(cpx& a, cpx& b) {
    cpx t{a.x - b.x, a.y - b.y};
    a = cpx{a.x + b.x, a.y + b.y};
    b = t;
}
template <int CONJ> __device__ __forceinline__ cpx mul_mi(cpx a) {
    return CONJ ? cpx{-a.y, a.x} : cpx{a.y, -a.x};
}
template <int CONJ> __device__ __forceinline__ cpx mul_w81(cpx a) {
    return CONJ ? cpx{C_SQ * (a.x - a.y), C_SQ * (a.y + a.x)}
                : cpx{C_SQ * (a.x + a.y), C_SQ * (a.y - a.x)};
}
template <int CONJ> __device__ __forceinline__ cpx mul_w83(cpx a) {
    return CONJ ? cpx{-C_SQ * (a.x + a.y), C_SQ * (a.x - a.y)}
                : cpx{C_SQ * (a.y - a.x), -C_SQ * (a.x + a.y)};
}

// radix-8 DIF butterfly; outputs bit-reversed: y_r = a[brev(r)], brev = 0,4,2,6,1,5,3,7
template <int CONJ> __device__ __forceinline__ void dft8(cpx a[8]) {
    fft2p(a[0], a[4]); fft2p(a[1], a[5]); fft2p(a[2], a[6]); fft2p(a[3], a[7]);
    a[5] = mul_w81<CONJ>(a[5]);
    a[6] = mul_mi<CONJ>(a[6]);
    a[7] = mul_w83<CONJ>(a[7]);
    fft2p(a[0], a[2]); fft2p(a[1], a[3]);
    a[3] = mul_mi<CONJ>(a[3]);
    fft2p(a[4], a[6]); fft2p(a[5], a[7]);
    a[7] = mul_mi<CONJ>(a[7]);
    fft2p(a[0], a[1]); fft2p(a[2], a[3]); fft2p(a[4], a[5]); fft2p(a[6], a[7]);
}
template <int CONJ> __device__ __forceinline__ void dft4(cpx a[4]) {
    fft2p(a[0], a[2]); fft2p(a[1], a[3]);
    a[3] = mul_mi<CONJ>(a[3]);
    fft2p(a[0], a[1]); fft2p(a[2], a[3]);
}

__device__ __forceinline__ float2 tw_lookup_g(int idx) {
    if (idx <= 1024) return g_T[idx];
    float2 u = g_T[2048 - idx];
    return make_float2(-u.x, u.y);
}

#define ST8(RE, IM, IDX0, STRIDE)                                              \
    do {                                                                       \
        cpx y;                                                                 \
        y = a[0];              RE[PADi((IDX0))] = y.x; IM[PADi((IDX0))] = y.y; \
        y = cmul(a[4], w1);    RE[PADi((IDX0) + (STRIDE))] = y.x; IM[PADi((IDX0) + (STRIDE))] = y.y; \
        y = cmul(a[2], w2);    RE[PADi((IDX0) + 2*(STRIDE))] = y.x; IM[PADi((IDX0) + 2*(STRIDE))] = y.y; \
        y = cmul(a[6], w3);    RE[PADi((IDX0) + 3*(STRIDE))] = y.x; IM[PADi((IDX0) + 3*(STRIDE))] = y.y; \
        y = cmul(a[1], w4);    RE[PADi((IDX0) + 4*(STRIDE))] = y.x; IM[PADi((IDX0) + 4*(STRIDE))] = y.y; \
        y = cmul(a[5], w5);    RE[PADi((IDX0) + 5*(STRIDE))] = y.x; IM[PADi((IDX0) + 5*(STRIDE))] = y.y; \
        y = cmul(a[3], w6);    RE[PADi((IDX0) + 6*(STRIDE))] = y.x; IM[PADi((IDX0) + 6*(STRIDE))] = y.y; \
        y = cmul(a[7], w7);    RE[PADi((IDX0) + 7*(STRIDE))] = y.x; IM[PADi((IDX0) + 7*(STRIDE))] = y.y; \
    } while (0)

#define MAKE_POWERS(base)                                                      \
    cpx w1 = base;                                                             \
    cpx w2 = cmul(w1, w1); cpx w3 = cmul(w2, w1); cpx w4 = cmul(w2, w2);       \
    cpx w5 = cmul(w4, w1); cpx w6 = cmul(w3, w3); cpx w7 = cmul(w4, w3)

template <int CONJ>
__device__ __forceinline__ void fft_passes_123(
    float* sRa, float* sIa, float* sRb, float* sIb, int t) {
    // pass1: B -> A   (s=8)
    {
        cpx a[8];
        #pragma unroll
        for (int r = 0; r < 8; r++) {
            int i = PADi(t + 256 * r);
            a[r] = cpx{sRb[i], sIb[i]};
        }
        dft8<CONJ>(a);
        int p = t >> 3, q = t & 7;
        float2 wb = g_T[16 * p];
        cpx base{wb.x, CONJ ? -wb.y : wb.y};
        MAKE_POWERS(base);
        int i0 = q + 64 * p;
        ST8(sRa, sIa, i0, 8);
    }
    __syncthreads();
    // pass2: A -> B   (s=64)
    {
        cpx a[8];
        int q = t & 63, p = t >> 6;
        #pragma unroll
        for (int r = 0; r < 8; r++) {
            int i = PADi(q + 64 * p + 256 * r);
            a[r] = cpx{sRa[i], sIa[i]};
        }
        dft8<CONJ>(a);
        float2 wb = g_T[128 * p];
        cpx base{wb.x, CONJ ? -wb.y : wb.y};
        MAKE_POWERS(base);
        int i0 = q + 512 * p;
        ST8(sRb, sIb, i0, 64);
    }
    __syncthreads();
}

// ---------------- K0: twiddle table + band indices (merged) ----------------
__global__ void k_init(const float* __restrict__ bb) {
    int k = blockIdx.x * 256 + threadIdx.x;
    if (k <= 1024) {
        float s, c;
        sincosf(CUDART_PI_F * (float)k / 2048.f, &s, &c);
        g_T[k] = make_float2(c, -s);
    }
    if (blockIdx.x == 0) {
        __shared__ int idx[9];
        if (threadIdx.x == 0) {
            float v[7];
            #pragma unroll
            for (int i = 0; i < 7; i++) v[i] = 1.f / (1.f + expf(-bb[i]));
            for (int i = 1; i < 7; i++) {
                float key = v[i]; int j = i - 1;
                while (j >= 0 && v[j] > key) { v[j + 1] = v[j]; j--; }
                v[j + 1] = key;
            }
            idx[0] = 0;
            for (int e = 1; e < 8; e++) {
                int t = (int)(v[e - 1] * 2049.0f);
                idx[e] = min(max(t, 0), 2049);
            }
            idx[8] = 2049;
        }
        __syncthreads();
        for (int f = threadIdx.x; f < Fn; f += 256) {
            int e = 0;
            #pragma unroll
            for (int t = 0; t < 8; t++)
                if (f >= idx[t] && f < idx[t + 1]) { e = t; break; }
            g_bandOf[f] = e;
        }
    }
}

// ---------------- K1: transpose x [B,L,N] -> g_xt [B,N,L] ----------------
__global__ void k_transpose_in(const float* __restrict__ x) {
    __shared__ float tile[32][33];
    int b = blockIdx.z;
    int l0 = blockIdx.x * 32, n0 = blockIdx.y * 32;
    int tx = threadIdx.x, ty = threadIdx.y;  // 8 x 32
    const float4* x4 = (const float4*)x;
    float4 v = x4[(((size_t)(b * Ln + l0 + ty)) * Nn + n0 + 4 * tx) >> 2];
    tile[ty][4 * tx + 0] = v.x;
    tile[ty][4 * tx + 1] = v.y;
    tile[ty][4 * tx + 2] = v.z;
    tile[ty][4 * tx + 3] = v.w;
    __syncthreads();
    float4 w;
    w.x = tile[4 * tx + 0][ty];
    w.y = tile[4 * tx + 1][ty];
    w.z = tile[4 * tx + 2][ty];
    w.w = tile[4 * tx + 3][ty];
    float4* o4 = (float4*)g_xt;
    o4[(((size_t)(b * Nn + n0 + ty)) * Ln + l0 + 4 * tx) >> 2] = w;
}

// ---------------- K2: per-series mean/var + rfft -> fp16 spectrum ----------------
__global__ __launch_bounds__(256) void k_fwd() {
    __shared__ float sRa[2304], sIa[2304], sRb[2304], sIb[2304];
    __shared__ float sred[16];
    int series = blockIdx.x;
    int t = threadIdx.x;
    const float2* row = (const float2*)(g_xt + (size_t)series * Ln);

    cpx a[8];
    float s1 = 0.f, s2 = 0.f;
    #pragma unroll
    for (int r = 0; r < 8; r++) {
        float2 v = row[t + 256 * r];
        a[r] = cpx{v.x, v.y};
        s1 += v.x + v.y;
        s2 += v.x * v.x + v.y * v.y;
    }
    #pragma unroll
    for (int off = 16; off; off >>= 1) {
        s1 += __shfl_down_sync(~0u, s1, off);
        s2 += __shfl_down_sync(~0u, s2, off);
    }
    if ((t & 31) == 0) { sred[t >> 5] = s1; sred[8 + (t >> 5)] = s2; }

    dft8<0>(a);
    {
        float2 wb = g_T[2 * t];
        cpx base{wb.x, wb.y};
        MAKE_POWERS(base);
        ST8(sRb, sIb, 8 * t, 1);
    }
    __syncthreads();
    if (t == 0) {
        float aa = 0.f, bb = 0.f;
        #pragma unroll
        for (int w = 0; w < 8; w++) { aa += sred[w]; bb += sred[8 + w]; }
        float mean = aa * (1.f / 4096.f);
        float var = bb * (1.f / 4096.f) - mean * mean + 1e-6f;
        g_mean[series] = mean;
        g_std[series]  = sqrtf(fmaxf(var, 0.f));
    }

    fft_passes_123<0>(sRa, sIa, sRb, sIb, t);

    // pass3: radix-4, B -> A
    #pragma unroll
    for (int uu = 0; uu < 2; uu++) {
        int u = t + 256 * uu;
        cpx c4[4];
        #pragma unroll
        for (int r = 0; r < 4; r++) {
            int i = PADi(u + 512 * r);
            c4[r] = cpx{sRb[i], sIb[i]};
        }
        dft4<0>(c4);
        sRa[PADi(u)]        = c4[0].x; sIa[PADi(u)]        = c4[0].y;
        sRa[PADi(u + 512)]  = c4[2].x; sIa[PADi(u + 512)]  = c4[2].y;
        sRa[PADi(u + 1024)] = c4[1].x; sIa[PADi(u + 1024)] = c4[1].y;
        sRa[PADi(u + 1536)] = c4[3].x; sIa[PADi(u + 1536)] = c4[3].y;
    }
    __syncthreads();

    // untangle packed FFT -> rfft bins, store fp16
    __half2* out = g_freq + (size_t)series * FS;
    for (int k = t; k < Fn; k += 256) {
        int ik = PADi(k & (N2h - 1));
        int imk = PADi((N2h - k) & (N2h - 1));
        cpx zk{sRa[ik], sIa[ik]};
        cpx zmk{sRa[imk], sIa[imk]};
        float2 A = make_float2(0.5f * (zk.x + zmk.x), 0.5f * (zk.y - zmk.y));
        float dx = zk.x - zmk.x, dy = zk.y + zmk.y;
        float2 Bv = make_float2(0.5f * dy, -0.5f * dx);
        float2 tw = tw_lookup_g(k);
        out[k] = __floats2half2_rn(A.x + tw.x * Bv.x - tw.y * Bv.y,
                                   A.y + tw.x * Bv.y + tw.y * Bv.x);
    }
}

// ---------------- K3: partial mag over n-half ----------------
__global__ __launch_bounds__(256) void k_mag() {
    int f = blockIdx.x * 256 + threadIdx.x;
    int b = blockIdx.y;
    int h = blockIdx.z;   // n half: 0 or 1
    if (f >= Fn) return;
    const __half2* base = g_freq + (size_t)b * Nn * FS + (size_t)h * 64 * FS + f;
    float acc[8];
    #pragma unroll
    for (int j = 0; j < 8; j++) acc[j] = 0.f;
    #pragma unroll 2
    for (int n0 = 0; n0 < 64; n0 += 8) {
        #pragma unroll
        for (int j = 0; j < 8; j++) {
            float2 v = __half22float2(base[(size_t)(n0 + j) * FS]);
            acc[j] += sqrtf(v.x * v.x + v.y * v.y);
        }
    }
    float s = ((acc[0] + acc[1]) + (acc[2] + acc[3])) +
              ((acc[4] + acc[5]) + (acc[6] + acc[7]));
    g_magp[h][f * 64 + b] = s;
}

// ---------------- K3b: merge partials -> magT ----------------
__global__ __launch_bounds__(256) void k_magred() {
    int i = blockIdx.x * 256 + threadIdx.x;
    if (i < Fn * 64)
        g_magT[i] = (g_magp[0][i] + g_magp[1][i]) * (1.f / 128.f);
}

// ---------------- K4a: GEMM partials, K-split ----------------
__global__ __launch_bounds__(256) void k_gemm1a(const float* __restrict__ w1) {
    int tid = threadIdx.x;
    int j = blockIdx.x * 64 + (tid & 63);
    int bg = tid >> 6;
    int ks = blockIdx.y;
    int kbeg = ks * KCH;
    int kend = min(kbeg + KCH, Fn);
    bool jok = (j < Fn);

    float acc[16];
    #pragma unroll
    for (int i = 0; i < 16; i++) acc[i] = 0.f;

    const float4* magT4 = (const float4*)g_magT;
    #pragma unroll 2
    for (int k = kbeg; k < kend; k++) {
        float wv = jok ? __ldg(&w1[(size_t)k * Fn + j]) : 0.f;
        const float4* mrow = magT4 + ((size_t)k << 4) + (bg << 2);
        float4 m0 = mrow[0], m1 = mrow[1], m2 = mrow[2], m3 = mrow[3];
        acc[0]  = fmaf(m0.x, wv, acc[0]);  acc[1]  = fmaf(m0.y, wv, acc[1]);
        acc[2]  = fmaf(m0.z, wv, acc[2]);  acc[3]  = fmaf(m0.w, wv, acc[3]);
        acc[4]  = fmaf(m1.x, wv, acc[4]);  acc[5]  = fmaf(m1.y, wv, acc[5]);
        acc[6]  = fmaf(m1.z, wv, acc[6]);  acc[7]  = fmaf(m1.w, wv, acc[7]);
        acc[8]  = fmaf(m2.x, wv, acc[8]);  acc[9]  = fmaf(m2.y, wv, acc[9]);
        acc[10] = fmaf(m2.z, wv, acc[10]); acc[11] = fmaf(m2.w, wv, acc[11]);
        acc[12] = fmaf(m3.x, wv, acc[12]); acc[13] = fmaf(m3.y, wv, acc[13]);
        acc[14] = fmaf(m3.z, wv, acc[14]); acc[15] = fmaf(m3.w, wv, acc[15]);
    }
    if (jok) {
        #pragma unroll
        for (int i = 0; i < 16; i++) {
            int b = 16 * bg + i;
            g_hp[((size_t)(ks * 64 + b)) * Fn + j] = acc[i];
        }
    }
}

// ---------------- K4b: reduce partials + bias + relu -> g_h ----------------
__global__ __launch_bounds__(256) void k_gemm1b(const float* __restrict__ b1) {
    int j = blockIdx.x * 256 + threadIdx.x;
    int b = blockIdx.y;
    if (j >= Fn) return;
    float s = 0.f;
    #pragma unroll
    for (int ks = 0; ks < KSPLIT; ks++)
        s += g_hp[((size_t)(ks * 64 + b)) * Fn + j];
    g_h[b * Fn + j] = fmaxf(s + b1[j], 0.f);
}

// ---------------- K5: logits -> softmax -> wmask ----------------
__global__ __launch_bounds__(256) void k_gate2(const float* __restrict__ w2,
                                               const float* __restrict__ b2) {
    __shared__ float slog[8];
    __shared__ float sw[8];
    int b = blockIdx.x;
    int tid = threadIdx.x, warp = tid >> 5, lane = tid & 31;
    float part = 0.f;
    for (int k = lane; k < Fn; k += 32)
        part += g_h[b * Fn + k] * w2[k * En + warp];
    #pragma unroll
    for (int off = 16; off; off >>= 1) part += __shfl_down_sync(~0u, part, off);
    if (lane == 0) slog[warp] = part + b2[warp];
    __syncthreads();
    if (tid == 0) {
        float mx = -1e30f;
        for (int e = 0; e < 8; e++) mx = fmaxf(mx, slog[e]);
        float s = 0.f, ex[8];
        for (int e = 0; e < 8; e++) { ex[e] = expf(slog[e] - mx); s += ex[e]; }
        float inv = 1.f / s;
        for (int e = 0; e < 8; e++) sw[e] = ex[e] * inv;
    }
    __syncthreads();
    for (int f = tid; f < Fn; f += 256)
        g_wmask[b * Fn + f] = sw[g_bandOf[f]];
}

// ---------------- K6: filter + irfft -> g_xt ----------------
__global__ __launch_bounds__(256) void k_inv() {
    __shared__ float sRa[2304], sIa[2304], sRb[2304], sIb[2304];
    int series = blockIdx.x;
    int b = series >> 7;
    int t = threadIdx.x;
    const __half2* Xg = g_freq + (size_t)series * FS;
    const float*   wm = g_wmask + b * Fn;

    // fused filter + repack: rfft bins -> Z[0..2047] directly into sA
    for (int k = t; k <= 1024; k += 256) {
        float2 vk = __half22float2(Xg[k]);
        float wk = wm[k];
        cpx Xk{vk.x * wk, vk.y * wk};
        int km = 2048 - k;
        float2 vm = __half22float2(Xg[km]);
        float wmk = wm[km];
        cpx Xmk{vm.x * wmk, vm.y * wmk};
        float2 A = make_float2(0.5f * (Xk.x + Xmk.x), 0.5f * (Xk.y - Xmk.y));
        float dx = Xk.x - Xmk.x, dy = Xk.y + Xmk.y;
        float2 tw = g_T[k];          // (cos, -sin)
        float c = tw.x, sn = -tw.y;
        float2 Bc = make_float2(0.5f * (c * dx - sn * dy), 0.5f * (c * dy + sn * dx));
        int ik = PADi(k);
        sRa[ik] = A.x - Bc.y;
        sIa[ik] = A.y + Bc.x;
        if (k >= 1 && k < 1024) {
            int imk = PADi(2048 - k);
            sRa[imk] = A.x + Bc.y;
            sIa[imk] = Bc.x - A.y;
        }
    }
    __syncthreads();

    // pass0: A -> B (inverse twiddles)
    {
        cpx a[8];
        #pragma unroll
        for (int r = 0; r < 8; r++) {
            int i = PADi(t + 256 * r);
            a[r] = cpx{sRa[i], sIa[i]};
        }
        dft8<1>(a);
        float2 wb = g_T[2 * t];
        cpx base{wb.x, -wb.y};
        MAKE_POWERS(base);
        ST8(sRb, sIb, 8 * t, 1);
    }
    __syncthreads();

    fft_passes_123<1>(sRa, sIa, sRb, sIb, t);

    // pass3: radix-4, B -> global (scale + mean)
    float2* outrow = (float2*)(g_xt + (size_t)series * Ln);
    float mean = g_mean[series];
    float stdv = g_std[series] * (1.f / 2048.f);
    #pragma unroll
    for (int uu = 0; uu < 2; uu++) {
        int u = t + 256 * uu;
        cpx c4[4];
        #pragma unroll
        for (int r = 0; r < 4; r++) {
            int i = PADi(u + 512 * r);
            c4[r] = cpx{sRb[i], sIb[i]};
        }
        dft4<1>(c4);
        outrow[u]        = make_float2(fmaf(c4[0].x, stdv, mean), fmaf(c4[0].y, stdv, mean));
        outrow[u + 512]  = make_float2(fmaf(c4[2].x, stdv, mean), fmaf(c4[2].y, stdv, mean));
        outrow[u + 1024] = make_float2(fmaf(c4[1].x, stdv, mean), fmaf(c4[1].y, stdv, mean));
        outrow[u + 1536] = make_float2(fmaf(c4[3].x, stdv, mean), fmaf(c4[3].y, stdv, mean));
    }
}

// ---------------- K7: out[b,l,n] = x[b,l,n] + rec[b,n,l] ----------------
__global__ void k_transpose_out(const float* __restrict__ x, float* __restrict__ out) {
    __shared__ float tile[32][33];
    int b = blockIdx.z;
    int l0 = blockIdx.x * 32, n0 = blockIdx.y * 32;
    int tx = threadIdx.x, ty = threadIdx.y;  // 8 x 32
    const float4* g4 = (const float4*)g_xt;
    float4 v = g4[(((size_t)(b * Nn + n0 + ty)) * Ln + l0 + 4 * tx) >> 2];
    tile[ty][4 * tx + 0] = v.x;
    tile[ty][4 * tx + 1] = v.y;
    tile[ty][4 * tx + 2] = v.z;
    tile[ty][4 * tx + 3] = v.w;
    __syncthreads();
    size_t idx = (((size_t)(b * Ln + l0 + ty)) * Nn + n0 + 4 * tx) >> 2;
    float4 xo = ((const float4*)x)[idx];
    float4 w;
    w.x = xo.x + tile[4 * tx + 0][ty];
    w.y = xo.y + tile[4 * tx + 1][ty];
    w.z = xo.z + tile[4 * tx + 2][ty];
    w.w = xo.w + tile[4 * tx + 3][ty];
    ((float4*)out)[idx] = w;
}

extern "C" void kernel_launch(void* const* d_in, const int* in_sizes, int n_in,
                              void* d_out, int out_size) {
    const float* x  = (const float*)d_in[0];
    const float* bb = (const float*)d_in[1];
    const float* w1 = (const float*)d_in[2];
    const float* b1 = (const float*)d_in[3];
    const float* w2 = (const float*)d_in[4];
    const float* b2 = (const float*)d_in[5];
    float* out = (float*)d_out;

    dim3 tb(8, 32);
    k_init<<<5, 256>>>(bb);
    k_transpose_in<<<dim3(128, 4, 64), tb>>>(x);
    k_fwd<<<NSER, 256>>>();
    k_mag<<<dim3(9, 64, 2), 256>>>();
    k_magred<<<513, 256>>>();
    k_gemm1a<<<dim3(33, KSPLIT), 256>>>(w1);
    k_gemm1b<<<dim3(9, 64), 256>>>(b1);
    k_gate2<<<64, 256>>>(w2, b2);
    k_inv<<<NSER, 256>>>();
    k_transpose_out<<<dim3(128, 4, 64), tb>>>(x, out);
}

// round 7
// speedup vs baseline: 2.3604x; 1.0486x over previous
#include <cuda_runtime.h>
#include <cuda_fp16.h>
#include <math_constants.h>

#define Bn 64
#define Ln 4096
#define Nn 128
#define Fn 2049
#define FS 2056          // padded row stride for g_freq (bins)
#define N2h 2048
#define En 8
#define NSER (Bn * Nn)   // 8192
#define KSPLIT 8
#define KCH 257          // 8*257 = 2056 >= 2049

#define C_SQ 0.70710678118654752f
#define PADi(i) ((i) + ((i) >> 3))

// ---------------- scratch ----------------
__device__ __half  g_xt[(size_t)NSER * Ln];     // fp16 time scratch (fwd input / rec output)
__device__ __half2 g_freq[(size_t)NSER * FS];   // fp16 spectrum (re,im)
__device__ float   g_mean[NSER];
__device__ float   g_std[NSER];
__device__ float   g_magp[2][Fn * 64];          // n-split partials [half][f*64+b]
__device__ float   g_magT[Fn * 64];             // [f][b]
__device__ float   g_hp[KSPLIT * 64 * Fn];      // gemm partials [ks][b][j]
__device__ float   g_h[Bn * Fn];
__device__ float   g_wmask[Bn * Fn];
__device__ int     g_bandOf[Fn];
__device__ float2  g_T[1025];   // T[i] = exp(-i*pi*i/2048), i=0..1024

struct cpx { float x, y; };
__device__ __forceinline__ cpx cmul(cpx a, cpx b) {
    return cpx{a.x * b.x - a.y * b.y, a.x * b.y + a.y * b.x};
}
__device__ __forceinline__ void fft2p(cpx& a, cpx& b) {
    cpx t{a.x - b.x, a.y - b.y};
    a = cpx{a.x + b.x, a.y + b.y};
    b = t;
}
template <int CONJ> __device__ __forceinline__ cpx mul_mi(cpx a) {
    return CONJ ? cpx{-a.y, a.x} : cpx{a.y, -a.x};
}
template <int CONJ> __device__ __forceinline__ cpx mul_w81(cpx a) {
    return CONJ ? cpx{C_SQ * (a.x - a.y), C_SQ * (a.y + a.x)}
                : cpx{C_SQ * (a.x + a.y), C_SQ * (a.y - a.x)};
}
template <int CONJ> __device__ __forceinline__ cpx mul_w83(cpx a) {
    return CONJ ? cpx{-C_SQ * (a.x + a.y), C_SQ * (a.x - a.y)}
                : cpx{C_SQ * (a.y - a.x), -C_SQ * (a.x + a.y)};
}

// radix-8 DIF butterfly; outputs bit-reversed: y_r = a[brev(r)], brev = 0,4,2,6,1,5,3,7
template <int CONJ> __device__ __forceinline__ void dft8(cpx a[8]) {
    fft2p(a[0], a[4]); fft2p(a[1], a[5]); fft2p(a[2], a[6]); fft2p(a[3], a[7]);
    a[5] = mul_w81<CONJ>(a[5]);
    a[6] = mul_mi<CONJ>(a[6]);
    a[7] = mul_w83<CONJ>(a[7]);
    fft2p(a[0], a[2]); fft2p(a[1], a[3]);
    a[3] = mul_mi<CONJ>(a[3]);
    fft2p(a[4], a[6]); fft2p(a[5], a[7]);
    a[7] = mul_mi<CONJ>(a[7]);
    fft2p(a[0], a[1]); fft2p(a[2], a[3]); fft2p(a[4], a[5]); fft2p(a[6], a[7]);
}
template <int CONJ> __device__ __forceinline__ void dft4(cpx a[4]) {
    fft2p(a[0], a[2]); fft2p(a[1], a[3]);
    a[3] = mul_mi<CONJ>(a[3]);
    fft2p(a[0], a[1]); fft2p(a[2], a[3]);
}

__device__ __forceinline__ float2 tw_lookup_g(int idx) {
    if (idx <= 1024) return g_T[idx];
    float2 u = g_T[2048 - idx];
    return make_float2(-u.x, u.y);
}

#define ST8(RE, IM, IDX0, STRIDE)                                              \
    do {                                                                       \
        cpx y;                                                                 \
        y = a[0];              RE[PADi((IDX0))] = y.x; IM[PADi((IDX0))] = y.y; \
        y = cmul(a[4], w1);    RE[PADi((IDX0) + (STRIDE))] = y.x; IM[PADi((IDX0) + (STRIDE))] = y.y; \
        y = cmul(a[2], w2);    RE[PADi((IDX0) + 2*(STRIDE))] = y.x; IM[PADi((IDX0) + 2*(STRIDE))] = y.y; \
        y = cmul(a[6], w3);    RE[PADi((IDX0) + 3*(STRIDE))] = y.x; IM[PADi((IDX0) + 3*(STRIDE))] = y.y; \
        y = cmul(a[1], w4);    RE[PADi((IDX0) + 4*(STRIDE))] = y.x; IM[PADi((IDX0) + 4*(STRIDE))] = y.y; \
        y = cmul(a[5], w5);    RE[PADi((IDX0) + 5*(STRIDE))] = y.x; IM[PADi((IDX0) + 5*(STRIDE))] = y.y; \
        y = cmul(a[3], w6);    RE[PADi((IDX0) + 6*(STRIDE))] = y.x; IM[PADi((IDX0) + 6*(STRIDE))] = y.y; \
        y = cmul(a[7], w7);    RE[PADi((IDX0) + 7*(STRIDE))] = y.x; IM[PADi((IDX0) + 7*(STRIDE))] = y.y; \
    } while (0)

#define MAKE_POWERS(base)                                                      \
    cpx w1 = base;                                                             \
    cpx w2 = cmul(w1, w1); cpx w3 = cmul(w2, w1); cpx w4 = cmul(w2, w2);       \
    cpx w5 = cmul(w4, w1); cpx w6 = cmul(w3, w3); cpx w7 = cmul(w4, w3)

template <int CONJ>
__device__ __forceinline__ void fft_passes_123(
    float* sRa, float* sIa, float* sRb, float* sIb, int t) {
    // pass1: B -> A   (s=8)
    {
        cpx a[8];
        #pragma unroll
        for (int r = 0; r < 8; r++) {
            int i = PADi(t + 256 * r);
            a[r] = cpx{sRb[i], sIb[i]};
        }
        dft8<CONJ>(a);
        int p = t >> 3, q = t & 7;
        float2 wb = g_T[16 * p];
        cpx base{wb.x, CONJ ? -wb.y : wb.y};
        MAKE_POWERS(base);
        int i0 = q + 64 * p;
        ST8(sRa, sIa, i0, 8);
    }
    __syncthreads();
    // pass2: A -> B   (s=64)
    {
        cpx a[8];
        int q = t & 63, p = t >> 6;
        #pragma unroll
        for (int r = 0; r < 8; r++) {
            int i = PADi(q + 64 * p + 256 * r);
            a[r] = cpx{sRa[i], sIa[i]};
        }
        dft8<CONJ>(a);
        float2 wb = g_T[128 * p];
        cpx base{wb.x, CONJ ? -wb.y : wb.y};
        MAKE_POWERS(base);
        int i0 = q + 512 * p;
        ST8(sRb, sIb, i0, 64);
    }
    __syncthreads();
}

// ---------------- K0: twiddle table + band indices ----------------
__global__ void k_init(const float* __restrict__ bb) {
    int k = blockIdx.x * 256 + threadIdx.x;
    if (k <= 1024) {
        float s, c;
        sincosf(CUDART_PI_F * (float)k / 2048.f, &s, &c);
        g_T[k] = make_float2(c, -s);
    }
    if (blockIdx.x == 0) {
        __shared__ int idx[9];
        if (threadIdx.x == 0) {
            float v[7];
            #pragma unroll
            for (int i = 0; i < 7; i++) v[i] = 1.f / (1.f + expf(-bb[i]));
            for (int i = 1; i < 7; i++) {
                float key = v[i]; int j = i - 1;
                while (j >= 0 && v[j] > key) { v[j + 1] = v[j]; j--; }
                v[j + 1] = key;
            }
            idx[0] = 0;
            for (int e = 1; e < 8; e++) {
                int t = (int)(v[e - 1] * 2049.0f);
                idx[e] = min(max(t, 0), 2049);
            }
            idx[8] = 2049;
        }
        __syncthreads();
        for (int f = threadIdx.x; f < Fn; f += 256) {
            int e = 0;
            #pragma unroll
            for (int t = 0; t < 8; t++)
                if (f >= idx[t] && f < idx[t + 1]) { e = t; break; }
            g_bandOf[f] = e;
        }
    }
}

// ---------------- K1: transpose x [B,L,N] -> g_xt fp16 [B,N,L] ----------------
__global__ void k_transpose_in(const float* __restrict__ x) {
    __shared__ float tile[32][33];
    int b = blockIdx.z;
    int l0 = blockIdx.x * 32, n0 = blockIdx.y * 32;
    int tx = threadIdx.x, ty = threadIdx.y;  // 8 x 32
    const float4* x4 = (const float4*)x;
    float4 v = x4[(((size_t)(b * Ln + l0 + ty)) * Nn + n0 + 4 * tx) >> 2];
    tile[ty][4 * tx + 0] = v.x;
    tile[ty][4 * tx + 1] = v.y;
    tile[ty][4 * tx + 2] = v.z;
    tile[ty][4 * tx + 3] = v.w;
    __syncthreads();
    __half2 h0 = __floats2half2_rn(tile[4 * tx + 0][ty], tile[4 * tx + 1][ty]);
    __half2 h1 = __floats2half2_rn(tile[4 * tx + 2][ty], tile[4 * tx + 3][ty]);
    uint2 pk;
    pk.x = *reinterpret_cast<unsigned*>(&h0);
    pk.y = *reinterpret_cast<unsigned*>(&h1);
    size_t base = ((size_t)(b * Nn + n0 + ty)) * Ln + l0 + 4 * tx;
    *reinterpret_cast<uint2*>(g_xt + base) = pk;
}

// ---------------- K2: per-series mean/var + rfft -> fp16 spectrum ----------------
__global__ __launch_bounds__(256) void k_fwd() {
    __shared__ float sRa[2304], sIa[2304], sRb[2304], sIb[2304];
    __shared__ float sred[16];
    int series = blockIdx.x;
    int t = threadIdx.x;
    const __half2* row = (const __half2*)(g_xt + (size_t)series * Ln);

    cpx a[8];
    float s1 = 0.f, s2 = 0.f;
    #pragma unroll
    for (int r = 0; r < 8; r++) {
        float2 v = __half22float2(row[t + 256 * r]);
        a[r] = cpx{v.x, v.y};
        s1 += v.x + v.y;
        s2 += v.x * v.x + v.y * v.y;
    }
    #pragma unroll
    for (int off = 16; off; off >>= 1) {
        s1 += __shfl_down_sync(~0u, s1, off);
        s2 += __shfl_down_sync(~0u, s2, off);
    }
    if ((t & 31) == 0) { sred[t >> 5] = s1; sred[8 + (t >> 5)] = s2; }

    dft8<0>(a);
    {
        float2 wb = g_T[2 * t];
        cpx base{wb.x, wb.y};
        MAKE_POWERS(base);
        ST8(sRb, sIb, 8 * t, 1);
    }
    __syncthreads();
    if (t == 0) {
        float aa = 0.f, bb = 0.f;
        #pragma unroll
        for (int w = 0; w < 8; w++) { aa += sred[w]; bb += sred[8 + w]; }
        float mean = aa * (1.f / 4096.f);
        float var = bb * (1.f / 4096.f) - mean * mean + 1e-6f;
        g_mean[series] = mean;
        g_std[series]  = sqrtf(fmaxf(var, 0.f));
    }

    fft_passes_123<0>(sRa, sIa, sRb, sIb, t);

    // pass3: radix-4, B -> A
    #pragma unroll
    for (int uu = 0; uu < 2; uu++) {
        int u = t + 256 * uu;
        cpx c4[4];
        #pragma unroll
        for (int r = 0; r < 4; r++) {
            int i = PADi(u + 512 * r);
            c4[r] = cpx{sRb[i], sIb[i]};
        }
        dft4<0>(c4);
        sRa[PADi(u)]        = c4[0].x; sIa[PADi(u)]        = c4[0].y;
        sRa[PADi(u + 512)]  = c4[2].x; sIa[PADi(u + 512)]  = c4[2].y;
        sRa[PADi(u + 1024)] = c4[1].x; sIa[PADi(u + 1024)] = c4[1].y;
        sRa[PADi(u + 1536)] = c4[3].x; sIa[PADi(u + 1536)] = c4[3].y;
    }
    __syncthreads();

    // untangle packed FFT -> rfft bins, store fp16
    __half2* out = g_freq + (size_t)series * FS;
    for (int k = t; k < Fn; k += 256) {
        int ik = PADi(k & (N2h - 1));
        int imk = PADi((N2h - k) & (N2h - 1));
        cpx zk{sRa[ik], sIa[ik]};
        cpx zmk{sRa[imk], sIa[imk]};
        float2 A = make_float2(0.5f * (zk.x + zmk.x), 0.5f * (zk.y - zmk.y));
        float dx = zk.x - zmk.x, dy = zk.y + zmk.y;
        float2 Bv = make_float2(0.5f * dy, -0.5f * dx);
        float2 tw = tw_lookup_g(k);
        out[k] = __floats2half2_rn(A.x + tw.x * Bv.x - tw.y * Bv.y,
                                   A.y + tw.x * Bv.y + tw.y * Bv.x);
    }
}

// ---------------- K3: partial mag over n-half, 2 bins/thread (8B loads) ----------------
__global__ __launch_bounds__(256) void k_mag() {
    int fp = blockIdx.x * 256 + threadIdx.x;   // bin pair index
    if (fp > 1024) return;
    int f = fp * 2;
    int b = blockIdx.y;
    int h = blockIdx.z;   // n half: 0 or 1
    const uint2* base = (const uint2*)(g_freq + (size_t)b * Nn * FS + (size_t)h * 64 * FS + f);
    float acc0[8], acc1[8];
    #pragma unroll
    for (int j = 0; j < 8; j++) { acc0[j] = 0.f; acc1[j] = 0.f; }
    #pragma unroll 2
    for (int n0 = 0; n0 < 64; n0 += 8) {
        #pragma unroll
        for (int j = 0; j < 8; j++) {
            uint2 pk = base[(size_t)(n0 + j) * (FS / 2)];
            float2 v0 = __half22float2(*reinterpret_cast<__half2*>(&pk.x));
            float2 v1 = __half22float2(*reinterpret_cast<__half2*>(&pk.y));
            acc0[j] += sqrtf(v0.x * v0.x + v0.y * v0.y);
            acc1[j] += sqrtf(v1.x * v1.x + v1.y * v1.y);
        }
    }
    float s0 = ((acc0[0] + acc0[1]) + (acc0[2] + acc0[3])) +
               ((acc0[4] + acc0[5]) + (acc0[6] + acc0[7]));
    float s1 = ((acc1[0] + acc1[1]) + (acc1[2] + acc1[3])) +
               ((acc1[4] + acc1[5]) + (acc1[6] + acc1[7]));
    g_magp[h][f * 64 + b] = s0;
    if (f + 1 < Fn) g_magp[h][(f + 1) * 64 + b] = s1;
}

// ---------------- K3b: merge partials -> magT ----------------
__global__ __launch_bounds__(256) void k_magred() {
    int i = blockIdx.x * 256 + threadIdx.x;
    if (i < Fn * 64)
        g_magT[i] = (g_magp[0][i] + g_magp[1][i]) * (1.f / 128.f);
}

// ---------------- K4a: GEMM partials, K-split ----------------
__global__ __launch_bounds__(256) void k_gemm1a(const float* __restrict__ w1) {
    int tid = threadIdx.x;
    int j = blockIdx.x * 64 + (tid & 63);
    int bg = tid >> 6;
    int ks = blockIdx.y;
    int kbeg = ks * KCH;
    int kend = min(kbeg + KCH, Fn);
    bool jok = (j < Fn);

    float acc[16];
    #pragma unroll
    for (int i = 0; i < 16; i++) acc[i] = 0.f;

    const float4* magT4 = (const float4*)g_magT;
    #pragma unroll 2
    for (int k = kbeg; k < kend; k++) {
        float wv = jok ? __ldg(&w1[(size_t)k * Fn + j]) : 0.f;
        const float4* mrow = magT4 + ((size_t)k << 4) + (bg << 2);
        float4 m0 = mrow[0], m1 = mrow[1], m2 = mrow[2], m3 = mrow[3];
        acc[0]  = fmaf(m0.x, wv, acc[0]);  acc[1]  = fmaf(m0.y, wv, acc[1]);
        acc[2]  = fmaf(m0.z, wv, acc[2]);  acc[3]  = fmaf(m0.w, wv, acc[3]);
        acc[4]  = fmaf(m1.x, wv, acc[4]);  acc[5]  = fmaf(m1.y, wv, acc[5]);
        acc[6]  = fmaf(m1.z, wv, acc[6]);  acc[7]  = fmaf(m1.w, wv, acc[7]);
        acc[8]  = fmaf(m2.x, wv, acc[8]);  acc[9]  = fmaf(m2.y, wv, acc[9]);
        acc[10] = fmaf(m2.z, wv, acc[10]); acc[11] = fmaf(m2.w, wv, acc[11]);
        acc[12] = fmaf(m3.x, wv, acc[12]); acc[13] = fmaf(m3.y, wv, acc[13]);
        acc[14] = fmaf(m3.z, wv, acc[14]); acc[15] = fmaf(m3.w, wv, acc[15]);
    }
    if (jok) {
        #pragma unroll
        for (int i = 0; i < 16; i++) {
            int b = 16 * bg + i;
            g_hp[((size_t)(ks * 64 + b)) * Fn + j] = acc[i];
        }
    }
}

// ---------------- K4b: reduce partials + bias + relu -> g_h ----------------
__global__ __launch_bounds__(256) void k_gemm1b(const float* __restrict__ b1) {
    int j = blockIdx.x * 256 + threadIdx.x;
    int b = blockIdx.y;
    if (j >= Fn) return;
    float s = 0.f;
    #pragma unroll
    for (int ks = 0; ks < KSPLIT; ks++)
        s += g_hp[((size_t)(ks * 64 + b)) * Fn + j];
    g_h[b * Fn + j] = fmaxf(s + b1[j], 0.f);
}

// ---------------- K5: logits -> softmax -> wmask ----------------
__global__ __launch_bounds__(256) void k_gate2(const float* __restrict__ w2,
                                               const float* __restrict__ b2) {
    __shared__ float slog[8];
    __shared__ float sw[8];
    int b = blockIdx.x;
    int tid = threadIdx.x, warp = tid >> 5, lane = tid & 31;
    float part = 0.f;
    for (int k = lane; k < Fn; k += 32)
        part += g_h[b * Fn + k] * w2[k * En + warp];
    #pragma unroll
    for (int off = 16; off; off >>= 1) part += __shfl_down_sync(~0u, part, off);
    if (lane == 0) slog[warp] = part + b2[warp];
    __syncthreads();
    if (tid == 0) {
        float mx = -1e30f;
        for (int e = 0; e < 8; e++) mx = fmaxf(mx, slog[e]);
        float s = 0.f, ex[8];
        for (int e = 0; e < 8; e++) { ex[e] = expf(slog[e] - mx); s += ex[e]; }
        float inv = 1.f / s;
        for (int e = 0; e < 8; e++) sw[e] = ex[e] * inv;
    }
    __syncthreads();
    for (int f = tid; f < Fn; f += 256)
        g_wmask[b * Fn + f] = sw[g_bandOf[f]];
}

// ---------------- K6: filter + irfft -> g_xt fp16 ----------------
__global__ __launch_bounds__(256) void k_inv() {
    __shared__ float sRa[2304], sIa[2304], sRb[2304], sIb[2304];
    int series = blockIdx.x;
    int b = series >> 7;
    int t = threadIdx.x;
    const __half2* Xg = g_freq + (size_t)series * FS;
    const float*   wm = g_wmask + b * Fn;

    // fused filter + repack: rfft bins -> Z[0..2047]
    for (int k = t; k <= 1024; k += 256) {
        float2 vk = __half22float2(Xg[k]);
        float wk = wm[k];
        cpx Xk{vk.x * wk, vk.y * wk};
        int km = 2048 - k;
        float2 vm = __half22float2(Xg[km]);
        float wmk = wm[km];
        cpx Xmk{vm.x * wmk, vm.y * wmk};
        float2 A = make_float2(0.5f * (Xk.x + Xmk.x), 0.5f * (Xk.y - Xmk.y));
        float dx = Xk.x - Xmk.x, dy = Xk.y + Xmk.y;
        float2 tw = g_T[k];          // (cos, -sin)
        float c = tw.x, sn = -tw.y;
        float2 Bc = make_float2(0.5f * (c * dx - sn * dy), 0.5f * (c * dy + sn * dx));
        int ik = PADi(k);
        sRa[ik] = A.x - Bc.y;
        sIa[ik] = A.y + Bc.x;
        if (k >= 1 && k < 1024) {
            int imk = PADi(2048 - k);
            sRa[imk] = A.x + Bc.y;
            sIa[imk] = Bc.x - A.y;
        }
    }
    __syncthreads();

    // pass0: A -> B (inverse twiddles)
    {
        cpx a[8];
        #pragma unroll
        for (int r = 0; r < 8; r++) {
            int i = PADi(t + 256 * r);
            a[r] = cpx{sRa[i], sIa[i]};
        }
        dft8<1>(a);
        float2 wb = g_T[2 * t];
        cpx base{wb.x, -wb.y};
        MAKE_POWERS(base);
        ST8(sRb, sIb, 8 * t, 1);
    }
    __syncthreads();

    fft_passes_123<1>(sRa, sIa, sRb, sIb, t);

    // pass3: radix-4, B -> global fp16 (scale + mean)
    __half2* outrow = (__half2*)(g_xt + (size_t)series * Ln);
    float mean = g_mean[series];
    float stdv = g_std[series] * (1.f / 2048.f);
    #pragma unroll
    for (int uu = 0; uu < 2; uu++) {
        int u = t + 256 * uu;
        cpx c4[4];
        #pragma unroll
        for (int r = 0; r < 4; r++) {
            int i = PADi(u + 512 * r);
            c4[r] = cpx{sRb[i], sIb[i]};
        }
        dft4<1>(c4);
        outrow[u]        = __floats2half2_rn(fmaf(c4[0].x, stdv, mean), fmaf(c4[0].y, stdv, mean));
        outrow[u + 512]  = __floats2half2_rn(fmaf(c4[2].x, stdv, mean), fmaf(c4[2].y, stdv, mean));
        outrow[u + 1024] = __floats2half2_rn(fmaf(c4[1].x, stdv, mean), fmaf(c4[1].y, stdv, mean));
        outrow[u + 1536] = __floats2half2_rn(fmaf(c4[3].x, stdv, mean), fmaf(c4[3].y, stdv, mean));
    }
}

// ---------------- K7: out[b,l,n] = x[b,l,n] + rec[b,n,l] ----------------
__global__ void k_transpose_out(const float* __restrict__ x, float* __restrict__ out) {
    __shared__ float tile[32][33];
    int b = blockIdx.z;
    int l0 = blockIdx.x * 32, n0 = blockIdx.y * 32;
    int tx = threadIdx.x, ty = threadIdx.y;  // 8 x 32
    size_t gbase = ((size_t)(b * Nn + n0 + ty)) * Ln + l0 + 4 * tx;
    uint2 pk = *reinterpret_cast<const uint2*>(g_xt + gbase);
    float2 v0 = __half22float2(*reinterpret_cast<__half2*>(&pk.x));
    float2 v1 = __half22float2(*reinterpret_cast<__half2*>(&pk.y));
    tile[ty][4 * tx + 0] = v0.x;
    tile[ty][4 * tx + 1] = v0.y;
    tile[ty][4 * tx + 2] = v1.x;
    tile[ty][4 * tx + 3] = v1.y;
    __syncthreads();
    size_t idx = (((size_t)(b * Ln + l0 + ty)) * Nn + n0 + 4 * tx) >> 2;
    float4 xo = ((const float4*)x)[idx];
    float4 w;
    w.x = xo.x + tile[4 * tx + 0][ty];
    w.y = xo.y + tile[4 * tx + 1][ty];
    w.z = xo.z + tile[4 * tx + 2][ty];
    w.w = xo.w + tile[4 * tx + 3][ty];
    ((float4*)out)[idx] = w;
}

extern "C" void kernel_launch(void* const* d_in, const int* in_sizes, int n_in,
                              void* d_out, int out_size) {
    const float* x  = (const float*)d_in[0];
    const float* bb = (const float*)d_in[1];
    const float* w1 = (const float*)d_in[2];
    const float* b1 = (const float*)d_in[3];
    const float* w2 = (const float*)d_in[4];
    const float* b2 = (const float*)d_in[5];
    float* out = (float*)d_out;

    dim3 tb(8, 32);
    k_init<<<5, 256>>>(bb);
    k_transpose_in<<<dim3(128, 4, 64), tb>>>(x);
    k_fwd<<<NSER, 256>>>();
    k_mag<<<dim3(5, 64, 2), 256>>>();
    k_magred<<<513, 256>>>();
    k_gemm1a<<<dim3(33, KSPLIT), 256>>>(w1);
    k_gemm1b<<<dim3(9, 64), 256>>>(b1);
    k_gate2<<<64, 256>>>(w2, b2);
    k_inv<<<NSER, 256>>>();
    k_transpose_out<<<dim3(128, 4, 64), tb>>>(x, out);
}